// round 5
// baseline (speedup 1.0000x reference)
#include <cuda_runtime.h>
#include <cuda_bf16.h>
#include <mma.h>
#include <cstdint>

using namespace nvcuda;

#define NBATCH 32
#define NPTS   1024
#define NCH    256
#define NPROP  256
#define NSAMP  16
#define OUTCH  119

#define OFF_OBJ     0
#define OFF_CENTER  16384
#define OFF_HS      40960
#define OFF_HRN     139264
#define OFF_HR      237568
#define OFF_SS      335872
#define OFF_SRN     483328
#define OFF_SR      925696
#define OFF_SEM     1368064
#define OFF_NEWXYZ  1515520
#define OFF_INDS    1540096

#define KP0   272            // layer-0 K padded (259 -> 17 chunks of 16)
#define LDA   280            // A smem leading dim (elements)

// ---------------- scratch (device globals; no allocs allowed) ----------------
__device__ int   g_inds[NBATCH * NPROP];
__device__ float g_newxyz[NBATCH * NPROP * 3];
__device__ int   g_idx[NBATCH * NPROP * NSAMP];
__device__ float g_feat[NBATCH * NPROP * 128];
// prepacked bf16 hi/lo weight images, row-major [K][128]
__device__ __align__(16) __nv_bfloat16 g_W0[2][KP0 * 128];
__device__ __align__(16) __nv_bfloat16 g_W1[2][128 * 128];
__device__ __align__(16) __nv_bfloat16 g_W2[2][128 * 128];

typedef wmma::fragment<wmma::matrix_a, 16, 16, 16, __nv_bfloat16, wmma::row_major> FragA;
typedef wmma::fragment<wmma::matrix_b, 16, 16, 16, __nv_bfloat16, wmma::row_major> FragB;
typedef wmma::fragment<wmma::accumulator, 16, 16, 16, float> FragC;

// ---------------- prepack: weights -> bf16 hi/lo row-major ----------------
__device__ __forceinline__ void split_store(float v, __nv_bfloat16* hi,
                                            __nv_bfloat16* lo, int idx) {
    __nv_bfloat16 h = __float2bfloat16(v);
    hi[idx] = h;
    lo[idx] = __float2bfloat16(v - __bfloat162float(h));
}
__global__ __launch_bounds__(256) void prepack_kernel(
    const float* __restrict__ w0, const float* __restrict__ w1,
    const float* __restrict__ w2) {
    const int nth = gridDim.x * blockDim.x;
    const int s0 = KP0 * 128, s1 = s0 + 16384, s2 = s1 + 16384;
    for (int t = blockIdx.x * blockDim.x + threadIdx.x; t < s2; t += nth) {
        if (t < s0) {
            const int k = t >> 7, n = t & 127;
            split_store((k < 259) ? w0[k * 128 + n] : 0.f, g_W0[0], g_W0[1], t);
        } else if (t < s1) {
            split_store(w1[t - s0], g_W1[0], g_W1[1], t - s0);
        } else {
            split_store(w2[t - s1], g_W2[0], g_W2[1], t - s1);
        }
    }
}

// ---------------- FPS (verified R1) ----------------
__global__ __launch_bounds__(1024) void fps_kernel(const float* __restrict__ xyz) {
    __shared__ float px[NPTS], py[NPTS], pz[NPTS];
    __shared__ float wv[32];
    __shared__ int   wi[32];
    __shared__ float lpt[3];
    const int b = blockIdx.x, tid = threadIdx.x;
    const float* xb = xyz + (size_t)b * NPTS * 3;
    float x = xb[tid * 3], y = xb[tid * 3 + 1], z = xb[tid * 3 + 2];
    px[tid] = x; py[tid] = y; pz[tid] = z;
    float dist = 1e10f;
    __syncthreads();
    if (tid == 0) {
        lpt[0] = px[0]; lpt[1] = py[0]; lpt[2] = pz[0];
        g_inds[b * NPROP] = 0;
        g_newxyz[b * NPROP * 3 + 0] = px[0];
        g_newxyz[b * NPROP * 3 + 1] = py[0];
        g_newxyz[b * NPROP * 3 + 2] = pz[0];
    }
    __syncthreads();
    for (int it = 1; it < NPROP; it++) {
        float dx = x - lpt[0], dy = y - lpt[1], dz = z - lpt[2];
        float d = __fadd_rn(__fadd_rn(__fmul_rn(dx, dx), __fmul_rn(dy, dy)), __fmul_rn(dz, dz));
        dist = fminf(dist, d);
        float v = dist; int id = tid;
        #pragma unroll
        for (int o = 16; o; o >>= 1) {
            float v2 = __shfl_xor_sync(0xffffffffu, v, o);
            int   i2 = __shfl_xor_sync(0xffffffffu, id, o);
            if (v2 > v || (v2 == v && i2 < id)) { v = v2; id = i2; }
        }
        if ((tid & 31) == 0) { wv[tid >> 5] = v; wi[tid >> 5] = id; }
        __syncthreads();
        if (tid < 32) {
            v = wv[tid]; id = wi[tid];
            #pragma unroll
            for (int o = 16; o; o >>= 1) {
                float v2 = __shfl_xor_sync(0xffffffffu, v, o);
                int   i2 = __shfl_xor_sync(0xffffffffu, id, o);
                if (v2 > v || (v2 == v && i2 < id)) { v = v2; id = i2; }
            }
            if (tid == 0) {
                g_inds[b * NPROP + it] = id;
                g_newxyz[(b * NPROP + it) * 3 + 0] = px[id];
                g_newxyz[(b * NPROP + it) * 3 + 1] = py[id];
                g_newxyz[(b * NPROP + it) * 3 + 2] = pz[id];
                lpt[0] = px[id]; lpt[1] = py[id]; lpt[2] = pz[id];
            }
        }
        __syncthreads();
    }
}

// ---------------- Ball query (verified R1) ----------------
__global__ __launch_bounds__(256) void ball_kernel(const float* __restrict__ xyz) {
    const int gw = (blockIdx.x * blockDim.x + threadIdx.x) >> 5;
    const int lane = threadIdx.x & 31;
    const int b = gw >> 8;
    const float cx = g_newxyz[gw * 3], cy = g_newxyz[gw * 3 + 1], cz = g_newxyz[gw * 3 + 2];
    const float* xb = xyz + (size_t)b * NPTS * 3;
    int cnt = 0, buf[NSAMP];
    for (int c0 = 0; c0 < NPTS; c0 += 32) {
        const int j = c0 + lane;
        float dx = xb[j * 3] - cx, dy = xb[j * 3 + 1] - cy, dz = xb[j * 3 + 2] - cz;
        float d = __fadd_rn(__fadd_rn(__fmul_rn(dx, dx), __fmul_rn(dy, dy)), __fmul_rn(dz, dz));
        unsigned m = __ballot_sync(0xffffffffu, d < 0.09f);
        if (lane == 0) {
            while (m && cnt < NSAMP) { int t = __ffs(m) - 1; buf[cnt++] = c0 + t; m &= m - 1; }
        }
        cnt = __shfl_sync(0xffffffffu, cnt, 0);
        if (cnt >= NSAMP) break;
    }
    if (lane == 0) {
        const int f = (cnt > 0) ? buf[0] : (NPTS - 1);
        for (int s = cnt; s < NSAMP; s++) buf[s] = f;
        for (int s = 0; s < NSAMP; s++) g_idx[gw * NSAMP + s] = buf[s];
    }
}

// ---------------- WMMA hi/lo split GEMM (M=128 x N=128, 8 warps) ----------
// Smem layout (dynamic, 32B-aligned sections):
//   Ah:      128*280 bf16  = 71680 B   @ 0
//   Al:      128*280 bf16  = 71680 B   @ 71680
//   Wch:     16*128  bf16  =  4096 B   @ 143360
//   Wcl:     16*128  bf16  =  4096 B   @ 147456
//   scratch: 8*16*20 f32   = 10240 B   @ 151552
#define MLP_SMEM 161792

__device__ __forceinline__ void gemm128(
    const __nv_bfloat16* Ah, const __nv_bfloat16* Al,
    const __nv_bfloat16* __restrict__ gWh, const __nv_bfloat16* __restrict__ gWl,
    int nchunk, __nv_bfloat16* Wch, __nv_bfloat16* Wcl,
    FragC acc[8], int tid, int w) {
    #pragma unroll
    for (int j = 0; j < 8; j++) wmma::fill_fragment(acc[j], 0.f);
    for (int kt = 0; kt < nchunk; kt++) {
        __syncthreads();
        ((uint4*)Wch)[tid] = ((const uint4*)(gWh + kt * 2048))[tid];
        ((uint4*)Wcl)[tid] = ((const uint4*)(gWl + kt * 2048))[tid];
        __syncthreads();
        FragA ah, al;
        wmma::load_matrix_sync(ah, Ah + w * 16 * LDA + kt * 16, LDA);
        wmma::load_matrix_sync(al, Al + w * 16 * LDA + kt * 16, LDA);
        #pragma unroll
        for (int j = 0; j < 8; j++) {
            FragB bh, bl;
            wmma::load_matrix_sync(bh, Wch + j * 16, 128);
            wmma::load_matrix_sync(bl, Wcl + j * 16, 128);
            wmma::mma_sync(acc[j], ah, bh, acc[j]);
            wmma::mma_sync(acc[j], ah, bl, acc[j]);
            wmma::mma_sync(acc[j], al, bh, acc[j]);
        }
    }
    __syncthreads();
}

// mid-layer epilogue: BN + ReLU, hi/lo split, write back as next A
__device__ __forceinline__ void epi_mid(
    FragC acc[8], float* sc, __nv_bfloat16* Ah, __nv_bfloat16* Al,
    const float* __restrict__ bb, const float* __restrict__ gg,
    const float* __restrict__ be, int w, int lane) {
    const int rr = lane >> 1, cc0 = (lane & 1) * 8;
    #pragma unroll
    for (int j = 0; j < 8; j++) {
        wmma::store_matrix_sync(sc, acc[j], 20, wmma::mem_row_major);
        __syncwarp();
        #pragma unroll
        for (int q = 0; q < 8; q++) {
            const int cc = cc0 + q, n = j * 16 + cc;
            const float x = sc[rr * 20 + cc];
            const float v = fmaxf(__ldg(gg + n) * (x + __ldg(bb + n)) + __ldg(be + n), 0.f);
            __nv_bfloat16 h = __float2bfloat16(v);
            Ah[(w * 16 + rr) * LDA + n] = h;
            Al[(w * 16 + rr) * LDA + n] = __float2bfloat16(v - __bfloat162float(h));
        }
        __syncwarp();
    }
}

__global__ __launch_bounds__(256, 1) void mlp_kernel(
    const float* __restrict__ xyz, const float* __restrict__ feats,
    const float* __restrict__ b0, const float* __restrict__ gg0, const float* __restrict__ be0,
    const float* __restrict__ b1, const float* __restrict__ gg1, const float* __restrict__ be1,
    const float* __restrict__ b2, const float* __restrict__ gg2, const float* __restrict__ be2) {
    extern __shared__ __align__(32) char dsm[];
    __nv_bfloat16* Ah  = (__nv_bfloat16*)dsm;
    __nv_bfloat16* Al  = (__nv_bfloat16*)(dsm + 71680);
    __nv_bfloat16* Wch = (__nv_bfloat16*)(dsm + 143360);
    __nv_bfloat16* Wcl = (__nv_bfloat16*)(dsm + 147456);
    float* scratch     = (float*)(dsm + 151552);
    __shared__ int jrow[128];

    const int tid = threadIdx.x;
    const int w = tid >> 5, lane = tid & 31;
    float* sc = scratch + w * 320;   // 16x20 per warp

    const int b = blockIdx.x >> 5, pt = (blockIdx.x & 31) << 3;

    // ---- gather: gxyz into cols 0..2, pad 259..271, feats into 3..258 ----
    if (tid < 128) {
        const int r = tid;
        const int gp = (b << 8) + pt + (r >> 4);
        const int j = g_idx[gp * NSAMP + (r & 15)];
        jrow[r] = j;
        const float* np = g_newxyz + gp * 3;
        const float* xp = xyz + ((size_t)b * NPTS + j) * 3;
        #pragma unroll
        for (int c = 0; c < 3; c++) {
            const float v = __fdiv_rn(xp[c] - np[c], 0.3f);
            __nv_bfloat16 h = __float2bfloat16(v);
            Ah[r * LDA + c] = h;
            Al[r * LDA + c] = __float2bfloat16(v - __bfloat162float(h));
        }
    }
    for (int e = tid; e < 128 * 16; e += 256) {
        const int r = e >> 4, k = 259 + (e & 15);
        if (k < KP0) {
            Ah[r * LDA + k] = __float2bfloat16(0.f);
            Al[r * LDA + k] = __float2bfloat16(0.f);
        }
    }
    __syncthreads();
    const float* fb = feats + (size_t)b * NPTS * NCH;
    for (int e = tid; e < 128 * NCH; e += 256) {
        const int r = e >> 8, c = e & 255;
        const float v = __ldg(fb + (size_t)jrow[r] * NCH + c);
        __nv_bfloat16 h = __float2bfloat16(v);
        Ah[r * LDA + 3 + c] = h;
        Al[r * LDA + 3 + c] = __float2bfloat16(v - __bfloat162float(h));
    }

    FragC acc[8];

    // ---- layer 0: K=272 ----
    gemm128(Ah, Al, g_W0[0], g_W0[1], KP0 / 16, Wch, Wcl, acc, tid, w);
    epi_mid(acc, sc, Ah, Al, b0, gg0, be0, w, lane);

    // ---- layer 1: K=128 ----
    gemm128(Ah, Al, g_W1[0], g_W1[1], 8, Wch, Wcl, acc, tid, w);
    epi_mid(acc, sc, Ah, Al, b1, gg1, be1, w, lane);

    // ---- layer 2: K=128, fused 16-sample maxpool (warp = 1 proposal) ----
    gemm128(Ah, Al, g_W2[0], g_W2[1], 8, Wch, Wcl, acc, tid, w);
    {
        const int gp = (b << 8) + pt + w;
        #pragma unroll
        for (int j = 0; j < 8; j++) {
            wmma::store_matrix_sync(sc, acc[j], 20, wmma::mem_row_major);
            __syncwarp();
            if (lane < 16) {
                const int n = j * 16 + lane;
                const float g = __ldg(gg2 + n), bbv = __ldg(b2 + n), bev = __ldg(be2 + n);
                float m = fmaxf(g * (sc[lane] + bbv) + bev, 0.f);
                #pragma unroll
                for (int rr = 1; rr < 16; rr++)
                    m = fmaxf(m, fmaxf(g * (sc[rr * 20 + lane] + bbv) + bev, 0.f));
                g_feat[((size_t)gp << 7) + n] = m;
            }
            __syncwarp();
        }
    }
}

// ---------------- SIMT head (verified R1) ----------------
__device__ __forceinline__ void gemm_tile(const float* A, const float* __restrict__ W,
                                          int ldw, int Kdim, int Ncols, float* wbuf,
                                          float acc[8][8], int tid, int tx, int ty) {
    for (int kt = 0; kt < Kdim; kt += 16) {
        int kc = Kdim - kt; if (kc > 16) kc = 16;
        __syncthreads();
        for (int e = tid; e < (kc << 7); e += 256) {
            const int kk = e >> 7, j = e & 127;
            wbuf[(kk << 7) + j] = (j < Ncols) ? W[(kt + kk) * ldw + j] : 0.f;
        }
        __syncthreads();
        #pragma unroll 4
        for (int kk = 0; kk < kc; kk++) {
            const float4* ap = (const float4*)(A + (kt + kk) * 132 + (ty << 3));
            float4 a0 = ap[0], a1 = ap[1];
            const float4* bpt = (const float4*)(wbuf + (kk << 7) + (tx << 3));
            float4 q0 = bpt[0], q1 = bpt[1];
            float av[8] = {a0.x, a0.y, a0.z, a0.w, a1.x, a1.y, a1.z, a1.w};
            float bv[8] = {q0.x, q0.y, q0.z, q0.w, q1.x, q1.y, q1.z, q1.w};
            #pragma unroll
            for (int i = 0; i < 8; i++)
                #pragma unroll
                for (int j = 0; j < 8; j++)
                    acc[i][j] = fmaf(av[i], bv[j], acc[i][j]);
        }
    }
    __syncthreads();
}

#define ZERO_ACC(acc)                  \
    _Pragma("unroll")                  \
    for (int _i = 0; _i < 8; _i++)     \
        _Pragma("unroll")              \
        for (int _j = 0; _j < 8; _j++) \
            acc[_i][_j] = 0.f;

#define HEAD_SMEM ((128 * 132 * 2 + 16 * 128 + 56) * 4)

__global__ __launch_bounds__(256, 1) void head_kernel(
    const float* __restrict__ w1, const float* __restrict__ b1,
    const float* __restrict__ gg1, const float* __restrict__ be1,
    const float* __restrict__ w2, const float* __restrict__ b2,
    const float* __restrict__ gg2, const float* __restrict__ be2,
    const float* __restrict__ w3, const float* __restrict__ b3,
    const float* __restrict__ msz, float* __restrict__ out) {
    extern __shared__ float sm[];
    float* a0 = sm;
    float* a1 = sm + 128 * 132;
    float* wbuf = a1 + 128 * 132;
    float* ms = wbuf + 16 * 128;

    const int tid = threadIdx.x;
    const int tx = tid & 15, ty = tid >> 4;
    const int gp0 = blockIdx.x << 7;

    if (tid < 54) ms[tid] = msz[tid];
    for (int e = tid; e < 16384; e += 256) {
        const int r = e >> 7, c = e & 127;
        a0[c * 132 + r] = g_feat[((size_t)(gp0 + r) << 7) + c];
    }

    float acc[8][8];
    const int j0 = tx << 3, r0 = ty << 3;

    ZERO_ACC(acc);
    gemm_tile(a0, w1, 128, 128, 128, wbuf, acc, tid, tx, ty);
    #pragma unroll
    for (int jj = 0; jj < 8; jj++) {
        const float g = gg1[j0 + jj], bb = b1[j0 + jj], be = be1[j0 + jj];
        float t[8];
        #pragma unroll
        for (int i = 0; i < 8; i++)
            t[i] = fminf(fmaxf(g * (acc[i][jj] + bb) + be, 0.f), 6.f);
        float* d = a1 + (j0 + jj) * 132 + r0;
        *(float4*)d = make_float4(t[0], t[1], t[2], t[3]);
        *(float4*)(d + 4) = make_float4(t[4], t[5], t[6], t[7]);
    }

    ZERO_ACC(acc);
    gemm_tile(a1, w2, 128, 128, 128, wbuf, acc, tid, tx, ty);
    #pragma unroll
    for (int jj = 0; jj < 8; jj++) {
        const float g = gg2[j0 + jj], bb = b2[j0 + jj], be = be2[j0 + jj];
        float t[8];
        #pragma unroll
        for (int i = 0; i < 8; i++)
            t[i] = fminf(fmaxf(g * (acc[i][jj] + bb) + be, 0.f), 6.f);
        float* d = a0 + (j0 + jj) * 132 + r0;
        *(float4*)d = make_float4(t[0], t[1], t[2], t[3]);
        *(float4*)(d + 4) = make_float4(t[4], t[5], t[6], t[7]);
    }

    ZERO_ACC(acc);
    gemm_tile(a0, w3, OUTCH, 128, OUTCH, wbuf, acc, tid, tx, ty);
    {
        float b3v[8];
        #pragma unroll
        for (int jj = 0; jj < 8; jj++)
            b3v[jj] = (j0 + jj < OUTCH) ? b3[j0 + jj] : 0.f;
        #pragma unroll
        for (int i = 0; i < 8; i++) {
            const int gp = gp0 + r0 + i;
            #pragma unroll
            for (int jj = 0; jj < 8; jj++) {
                const int j = j0 + jj;
                if (j >= OUTCH) continue;
                const float v = acc[i][jj] + b3v[jj];
                if (j < 3) {
                    out[OFF_CENTER + gp * 3 + j] = g_newxyz[gp * 3 + j] + v;
                } else {
                    const int jr = j - 3;
                    if (jr < 2)        out[OFF_OBJ + gp * 2 + jr] = v;
                    else if (jr < 14)  out[OFF_HS + gp * 12 + (jr - 2)] = v;
                    else if (jr < 32)  out[OFF_SS + gp * 18 + (jr - 14)] = v;
                    else if (jr < 44) {
                        const int h = jr - 32;
                        out[OFF_HRN + gp * 12 + h] = v;
                        out[OFF_HR + gp * 12 + h] = v * 0.26179938779916667f;
                    } else if (jr < 98) {
                        const int t = jr - 44;
                        out[OFF_SRN + gp * 54 + t] = v;
                        out[OFF_SR + gp * 54 + t] = v * ms[t];
                    } else out[OFF_SEM + gp * 18 + (jr - 98)] = v;
                }
            }
        }
    }
}

__global__ __launch_bounds__(256) void tail_kernel(float* __restrict__ out) {
    const int i = blockIdx.x * blockDim.x + threadIdx.x;
    if (i < NBATCH * NPROP * 3) out[OFF_NEWXYZ + i] = g_newxyz[i];
    else if (i < NBATCH * NPROP * 4) {
        const int k = i - NBATCH * NPROP * 3;
        out[OFF_INDS + k] = (float)g_inds[k];
    }
}

extern "C" void kernel_launch(void* const* d_in, const int* in_sizes, int n_in,
                              void* d_out, int out_size) {
    const float* xyz   = (const float*)d_in[0];
    const float* feats = (const float*)d_in[1];
    const float* msz   = (const float*)d_in[2];
    const float* w_m0  = (const float*)d_in[3];
    const float* b_m0  = (const float*)d_in[4];
    const float* g_m0  = (const float*)d_in[5];
    const float* be_m0 = (const float*)d_in[6];
    const float* w_m1  = (const float*)d_in[7];
    const float* b_m1  = (const float*)d_in[8];
    const float* g_m1  = (const float*)d_in[9];
    const float* be_m1 = (const float*)d_in[10];
    const float* w_m2  = (const float*)d_in[11];
    const float* b_m2  = (const float*)d_in[12];
    const float* g_m2  = (const float*)d_in[13];
    const float* be_m2 = (const float*)d_in[14];
    const float* w1    = (const float*)d_in[15];
    const float* b1    = (const float*)d_in[16];
    const float* g1    = (const float*)d_in[17];
    const float* be1   = (const float*)d_in[18];
    const float* w2    = (const float*)d_in[19];
    const float* b2    = (const float*)d_in[20];
    const float* g2    = (const float*)d_in[21];
    const float* be2   = (const float*)d_in[22];
    const float* w3    = (const float*)d_in[23];
    const float* b3    = (const float*)d_in[24];
    float* out = (float*)d_out;

    cudaFuncSetAttribute(mlp_kernel, cudaFuncAttributeMaxDynamicSharedMemorySize, MLP_SMEM);
    cudaFuncSetAttribute(head_kernel, cudaFuncAttributeMaxDynamicSharedMemorySize, HEAD_SMEM);

    prepack_kernel<<<68, 256>>>(w_m0, w_m1, w_m2);
    fps_kernel<<<NBATCH, 1024>>>(xyz);
    ball_kernel<<<(NBATCH * NPROP * 32) / 256, 256>>>(xyz);
    mlp_kernel<<<NBATCH * (NPROP / 8), 256, MLP_SMEM>>>(
        xyz, feats, b_m0, g_m0, be_m0, b_m1, g_m1, be_m1, b_m2, g_m2, be_m2);
    head_kernel<<<(NBATCH * NPROP) / 128, 256, HEAD_SMEM>>>(
        w1, b1, g1, be1, w2, b2, g2, be2, w3, b3, msz, out);
    tail_kernel<<<(NBATCH * NPROP * 4 + 255) / 256, 256>>>(out);
}

// round 6
// speedup vs baseline: 2.8969x; 2.8969x over previous
#include <cuda_runtime.h>
#include <cuda_bf16.h>
#include <cstdint>

#define NBATCH 32
#define NPTS   1024
#define NCH    256
#define NPROP  256
#define NSAMP  16
#define OUTCH  119

#define OFF_OBJ     0
#define OFF_CENTER  16384
#define OFF_HS      40960
#define OFF_HRN     139264
#define OFF_HR      237568
#define OFF_SS      335872
#define OFF_SRN     483328
#define OFF_SR      925696
#define OFF_SEM     1368064
#define OFF_NEWXYZ  1515520
#define OFF_INDS    1540096

#define KP0   272               // layer-0 MMA K (256 feats + 3 gxyz + pad), 17 chunks
#define LDA   280               // A smem leading dim (bf16 elems); 560B rows, conflict-free
#define MLP_SMEM (64 * LDA * 2 * 2)   // Ah + Al = 71680 B

// ---------------- scratch ----------------
__device__ int   g_inds[NBATCH * NPROP];
__device__ float g_newxyz[NBATCH * NPROP * 3];
__device__ int   g_idx[NBATCH * NPROP * NSAMP];
__device__ float g_feat[NBATCH * NPROP * 128];
// B fragments prepacked in mma-lane order: [chunk][jtile(16)][lane(32)][reg(2)] u32
__device__ __align__(16) uint32_t g_W0p[2][17 * 1024];
__device__ __align__(16) uint32_t g_W1p[2][8 * 1024];
__device__ __align__(16) uint32_t g_W2p[2][8 * 1024];

// ---------------- helpers ----------------
__device__ __forceinline__ uint32_t smem_u32(const void* p) {
    uint32_t a;
    asm("{ .reg .u64 t; cvta.to.shared.u64 t, %1; cvt.u32.u64 %0, t; }" : "=r"(a) : "l"(p));
    return a;
}
__device__ __forceinline__ uint32_t pack_bf2(float a, float b) {
    __nv_bfloat16 ha = __float2bfloat16(a), hb = __float2bfloat16(b);
    return (uint32_t)__bfloat16_as_ushort(ha) | ((uint32_t)__bfloat16_as_ushort(hb) << 16);
}
__device__ __forceinline__ uint32_t pack_lo2(float a, float b) {
    float ra = a - __bfloat162float(__float2bfloat16(a));
    float rb = b - __bfloat162float(__float2bfloat16(b));
    return pack_bf2(ra, rb);
}
__device__ __forceinline__ void ldsm4(uint32_t r[4], uint32_t addr) {
    asm volatile("ldmatrix.sync.aligned.m8n8.x4.shared.b16 {%0,%1,%2,%3}, [%4];"
                 : "=r"(r[0]), "=r"(r[1]), "=r"(r[2]), "=r"(r[3]) : "r"(addr));
}
__device__ __forceinline__ void mma16816(float d[4], const uint32_t a[4],
                                         uint32_t b0, uint32_t b1) {
    asm volatile("mma.sync.aligned.m16n8k16.row.col.f32.bf16.bf16.f32 "
                 "{%0,%1,%2,%3}, {%4,%5,%6,%7}, {%8,%9}, {%0,%1,%2,%3};"
                 : "+f"(d[0]), "+f"(d[1]), "+f"(d[2]), "+f"(d[3])
                 : "r"(a[0]), "r"(a[1]), "r"(a[2]), "r"(a[3]), "r"(b0), "r"(b1));
}

// ---------------- prepack: weights -> lane-order B fragments ----------------
// u32 idx decode: c=idx>>10, j=(idx>>6)&15, lane=(idx>>1)&31, rr=idx&1
// element pair: k0 = c*16 + (lane&3)*2 + rr*8, k1=k0+1; n = j*8 + (lane>>2)
__device__ __forceinline__ float w0v(const float* __restrict__ w0, int k, int n) {
    // A layer-0 col order: 0..255 = feats (orig rows 3..258), 256..258 = gxyz (rows 0..2)
    if (k < 256) return w0[(3 + k) * 128 + n];
    if (k < 259) return w0[(k - 256) * 128 + n];
    return 0.f;
}
__global__ __launch_bounds__(256) void prepack_kernel(
    const float* __restrict__ w0, const float* __restrict__ w1,
    const float* __restrict__ w2) {
    const int nth = gridDim.x * blockDim.x;
    const int s0 = 17 * 1024, s1 = s0 + 8 * 1024, s2 = s1 + 8 * 1024;
    for (int t = blockIdx.x * blockDim.x + threadIdx.x; t < s2; t += nth) {
        int idx, which;
        if (t < s0) { idx = t; which = 0; }
        else if (t < s1) { idx = t - s0; which = 1; }
        else { idx = t - s1; which = 2; }
        const int c = idx >> 10, j = (idx >> 6) & 15, lane = (idx >> 1) & 31, rr = idx & 1;
        const int k0 = c * 16 + (lane & 3) * 2 + rr * 8;
        const int n = j * 8 + (lane >> 2);
        float v0, v1;
        if (which == 0) { v0 = w0v(w0, k0, n); v1 = w0v(w0, k0 + 1, n); }
        else {
            const float* w = (which == 1) ? w1 : w2;
            v0 = w[k0 * 128 + n]; v1 = w[(k0 + 1) * 128 + n];
        }
        uint32_t hi = pack_bf2(v0, v1), lo = pack_lo2(v0, v1);
        if (which == 0) { g_W0p[0][idx] = hi; g_W0p[1][idx] = lo; }
        else if (which == 1) { g_W1p[0][idx] = hi; g_W1p[1][idx] = lo; }
        else { g_W2p[0][idx] = hi; g_W2p[1][idx] = lo; }
    }
}

// ---------------- FPS (verified) ----------------
__global__ __launch_bounds__(1024) void fps_kernel(const float* __restrict__ xyz) {
    __shared__ float px[NPTS], py[NPTS], pz[NPTS];
    __shared__ float wv[32];
    __shared__ int   wi[32];
    __shared__ float lpt[3];
    const int b = blockIdx.x, tid = threadIdx.x;
    const float* xb = xyz + (size_t)b * NPTS * 3;
    float x = xb[tid * 3], y = xb[tid * 3 + 1], z = xb[tid * 3 + 2];
    px[tid] = x; py[tid] = y; pz[tid] = z;
    float dist = 1e10f;
    __syncthreads();
    if (tid == 0) {
        lpt[0] = px[0]; lpt[1] = py[0]; lpt[2] = pz[0];
        g_inds[b * NPROP] = 0;
        g_newxyz[b * NPROP * 3 + 0] = px[0];
        g_newxyz[b * NPROP * 3 + 1] = py[0];
        g_newxyz[b * NPROP * 3 + 2] = pz[0];
    }
    __syncthreads();
    for (int it = 1; it < NPROP; it++) {
        float dx = x - lpt[0], dy = y - lpt[1], dz = z - lpt[2];
        float d = __fadd_rn(__fadd_rn(__fmul_rn(dx, dx), __fmul_rn(dy, dy)), __fmul_rn(dz, dz));
        dist = fminf(dist, d);
        float v = dist; int id = tid;
        #pragma unroll
        for (int o = 16; o; o >>= 1) {
            float v2 = __shfl_xor_sync(0xffffffffu, v, o);
            int   i2 = __shfl_xor_sync(0xffffffffu, id, o);
            if (v2 > v || (v2 == v && i2 < id)) { v = v2; id = i2; }
        }
        if ((tid & 31) == 0) { wv[tid >> 5] = v; wi[tid >> 5] = id; }
        __syncthreads();
        if (tid < 32) {
            v = wv[tid]; id = wi[tid];
            #pragma unroll
            for (int o = 16; o; o >>= 1) {
                float v2 = __shfl_xor_sync(0xffffffffu, v, o);
                int   i2 = __shfl_xor_sync(0xffffffffu, id, o);
                if (v2 > v || (v2 == v && i2 < id)) { v = v2; id = i2; }
            }
            if (tid == 0) {
                g_inds[b * NPROP + it] = id;
                g_newxyz[(b * NPROP + it) * 3 + 0] = px[id];
                g_newxyz[(b * NPROP + it) * 3 + 1] = py[id];
                g_newxyz[(b * NPROP + it) * 3 + 2] = pz[id];
                lpt[0] = px[id]; lpt[1] = py[id]; lpt[2] = pz[id];
            }
        }
        __syncthreads();
    }
}

// ---------------- Ball query (verified) ----------------
__global__ __launch_bounds__(256) void ball_kernel(const float* __restrict__ xyz) {
    const int gw = (blockIdx.x * blockDim.x + threadIdx.x) >> 5;
    const int lane = threadIdx.x & 31;
    const int b = gw >> 8;
    const float cx = g_newxyz[gw * 3], cy = g_newxyz[gw * 3 + 1], cz = g_newxyz[gw * 3 + 2];
    const float* xb = xyz + (size_t)b * NPTS * 3;
    int cnt = 0, buf[NSAMP];
    for (int c0 = 0; c0 < NPTS; c0 += 32) {
        const int j = c0 + lane;
        float dx = xb[j * 3] - cx, dy = xb[j * 3 + 1] - cy, dz = xb[j * 3 + 2] - cz;
        float d = __fadd_rn(__fadd_rn(__fmul_rn(dx, dx), __fmul_rn(dy, dy)), __fmul_rn(dz, dz));
        unsigned m = __ballot_sync(0xffffffffu, d < 0.09f);
        if (lane == 0) {
            while (m && cnt < NSAMP) { int t = __ffs(m) - 1; buf[cnt++] = c0 + t; m &= m - 1; }
        }
        cnt = __shfl_sync(0xffffffffu, cnt, 0);
        if (cnt >= NSAMP) break;
    }
    if (lane == 0) {
        const int f = (cnt > 0) ? buf[0] : (NPTS - 1);
        for (int s = cnt; s < NSAMP; s++) buf[s] = f;
        for (int s = 0; s < NSAMP; s++) g_idx[gw * NSAMP + s] = buf[s];
    }
}

// ---------------- mma MLP: warp = 1 proposal, no block syncs ----------------
__device__ __forceinline__ void run_layer(float acc[16][4], uint32_t aH, uint32_t aL,
                                          const uint2* __restrict__ Wh,
                                          const uint2* __restrict__ Wl,
                                          int nchunk, int lane) {
    for (int kt = 0; kt < nchunk; kt++) {
        uint32_t ah[4], al[4];
        ldsm4(ah, aH + kt * 32);
        ldsm4(al, aL + kt * 32);
        uint2 bh[16], bl[16];
        #pragma unroll
        for (int j = 0; j < 16; j++) bh[j] = __ldg(Wh + (kt * 16 + j) * 32 + lane);
        #pragma unroll
        for (int j = 0; j < 16; j++) bl[j] = __ldg(Wl + (kt * 16 + j) * 32 + lane);
        #pragma unroll
        for (int j = 0; j < 16; j++) {
            mma16816(acc[j], ah, bh[j].x, bh[j].y);
            mma16816(acc[j], al, bh[j].x, bh[j].y);
            mma16816(acc[j], ah, bl[j].x, bl[j].y);
        }
    }
}

__device__ __forceinline__ void epi_mid(float acc[16][4], __nv_bfloat16* Ah,
                                        __nv_bfloat16* Al,
                                        const float* __restrict__ bb,
                                        const float* __restrict__ gg,
                                        const float* __restrict__ be,
                                        int w, int lane) {
    const int g = lane >> 2, t = lane & 3;
    const int rA = w * 16 + g, rB = rA + 8;
    #pragma unroll
    for (int j = 0; j < 16; j++) {
        const int n0 = j * 8 + t * 2, n1 = n0 + 1;
        const float g0 = __ldg(gg + n0), g1 = __ldg(gg + n1);
        const float c0 = __ldg(bb + n0), c1 = __ldg(bb + n1);
        const float e0 = __ldg(be + n0), e1 = __ldg(be + n1);
        float v00 = fmaxf(g0 * (acc[j][0] + c0) + e0, 0.f);
        float v01 = fmaxf(g1 * (acc[j][1] + c1) + e1, 0.f);
        float v10 = fmaxf(g0 * (acc[j][2] + c0) + e0, 0.f);
        float v11 = fmaxf(g1 * (acc[j][3] + c1) + e1, 0.f);
        *(uint32_t*)(Ah + rA * LDA + n0) = pack_bf2(v00, v01);
        *(uint32_t*)(Ah + rB * LDA + n0) = pack_bf2(v10, v11);
        *(uint32_t*)(Al + rA * LDA + n0) = pack_lo2(v00, v01);
        *(uint32_t*)(Al + rB * LDA + n0) = pack_lo2(v10, v11);
        acc[j][0] = acc[j][1] = acc[j][2] = acc[j][3] = 0.f;
    }
    __syncwarp();
}

__global__ __launch_bounds__(128, 3) void mlp_kernel(
    const float* __restrict__ xyz, const float* __restrict__ feats,
    const float* __restrict__ b0, const float* __restrict__ gg0, const float* __restrict__ be0,
    const float* __restrict__ b1, const float* __restrict__ gg1, const float* __restrict__ be1,
    const float* __restrict__ b2, const float* __restrict__ gg2, const float* __restrict__ be2) {
    extern __shared__ __align__(16) char dsm[];
    __nv_bfloat16* Ah = (__nv_bfloat16*)dsm;            // 64 x LDA
    __nv_bfloat16* Al = Ah + 64 * LDA;

    const int tid = threadIdx.x, w = tid >> 5, lane = tid & 31;
    const int p = blockIdx.x * 4 + w;                   // global proposal
    const int b = p >> 8;

    // ---- gather (warp-private rows w*16 .. w*16+15) ----
    int jloc = (lane < 16) ? g_idx[p * NSAMP + lane] : 0;
    const float* fb = feats + (size_t)b * NPTS * NCH;
    #pragma unroll 1
    for (int s = 0; s < 16; s++) {
        const int j = __shfl_sync(0xffffffffu, jloc, s);
        const int row = w * 16 + s;
        const float4* src = (const float4*)(fb + (size_t)j * NCH);
        float4 f0 = src[lane * 2], f1 = src[lane * 2 + 1];
        uint4 H, L;
        H.x = pack_bf2(f0.x, f0.y); H.y = pack_bf2(f0.z, f0.w);
        H.z = pack_bf2(f1.x, f1.y); H.w = pack_bf2(f1.z, f1.w);
        L.x = pack_lo2(f0.x, f0.y); L.y = pack_lo2(f0.z, f0.w);
        L.z = pack_lo2(f1.x, f1.y); L.w = pack_lo2(f1.z, f1.w);
        *(uint4*)(Ah + row * LDA + lane * 8) = H;
        *(uint4*)(Al + row * LDA + lane * 8) = L;
    }
    if (lane < 16) {
        const int row = w * 16 + lane;
        const float* np = g_newxyz + p * 3;
        const float* xp = xyz + ((size_t)b * NPTS + jloc) * 3;
        #pragma unroll
        for (int c = 0; c < 3; c++) {
            const float v = __fdiv_rn(xp[c] - np[c], 0.3f);
            __nv_bfloat16 h = __float2bfloat16(v);
            Ah[row * LDA + 256 + c] = h;
            Al[row * LDA + 256 + c] = __float2bfloat16(v - __bfloat162float(h));
        }
        for (int c = 259; c < KP0; c++) {
            Ah[row * LDA + c] = __float2bfloat16(0.f);
            Al[row * LDA + c] = __float2bfloat16(0.f);
        }
    }
    __syncwarp();

    float acc[16][4];
    #pragma unroll
    for (int j = 0; j < 16; j++)
        acc[j][0] = acc[j][1] = acc[j][2] = acc[j][3] = 0.f;

    const uint32_t aOff = ((w * 16 + (lane & 15)) * LDA + (lane >> 4) * 8) * 2;
    const uint32_t aH = smem_u32(Ah) + aOff;
    const uint32_t aL = smem_u32(Al) + aOff;

    run_layer(acc, aH, aL, (const uint2*)g_W0p[0], (const uint2*)g_W0p[1], 17, lane);
    epi_mid(acc, Ah, Al, b0, gg0, be0, w, lane);
    run_layer(acc, aH, aL, (const uint2*)g_W1p[0], (const uint2*)g_W1p[1], 8, lane);
    epi_mid(acc, Ah, Al, b1, gg1, be1, w, lane);
    run_layer(acc, aH, aL, (const uint2*)g_W2p[0], (const uint2*)g_W2p[1], 8, lane);

    // ---- maxpool epilogue: warp's 16 rows = proposal's 16 samples ----
    {
        const int t = lane & 3;
        #pragma unroll
        for (int j = 0; j < 16; j++) {
            const int n0 = j * 8 + t * 2, n1 = n0 + 1;
            const float g0 = __ldg(gg2 + n0), g1 = __ldg(gg2 + n1);
            const float c0 = __ldg(b2 + n0), c1 = __ldg(b2 + n1);
            const float e0 = __ldg(be2 + n0), e1 = __ldg(be2 + n1);
            float m0 = fmaxf(fmaxf(g0 * (acc[j][0] + c0) + e0, 0.f),
                             fmaxf(g0 * (acc[j][2] + c0) + e0, 0.f));
            float m1 = fmaxf(fmaxf(g1 * (acc[j][1] + c1) + e1, 0.f),
                             fmaxf(g1 * (acc[j][3] + c1) + e1, 0.f));
            #pragma unroll
            for (int o = 4; o <= 16; o <<= 1) {
                m0 = fmaxf(m0, __shfl_xor_sync(0xffffffffu, m0, o));
                m1 = fmaxf(m1, __shfl_xor_sync(0xffffffffu, m1, o));
            }
            if (lane < 4)
                *(float2*)(g_feat + ((size_t)p << 7) + n0) = make_float2(m0, m1);
        }
    }
}

// ---------------- head: 32-row tiles, 256 blocks ----------------
#define LDH 36
#define HEAD_SMEM ((128 * LDH * 2 + 16 * 128 + 56) * 4)

__device__ __forceinline__ void gemm_tile32(const float* A, const float* __restrict__ W,
                                            int ldw, int Ncols, float* wbuf,
                                            float acc[2][8], int tid, int tx, int ty) {
    for (int kt = 0; kt < 128; kt += 16) {
        __syncthreads();
        for (int e = tid; e < 2048; e += 256) {
            const int kk = e >> 7, j = e & 127;
            wbuf[e] = (j < Ncols) ? W[(kt + kk) * ldw + j] : 0.f;
        }
        __syncthreads();
        #pragma unroll 4
        for (int kk = 0; kk < 16; kk++) {
            const float2 a = *(const float2*)(A + (kt + kk) * LDH + ty * 2);
            const float4* bp = (const float4*)(wbuf + (kk << 7) + (tx << 3));
            const float4 q0 = bp[0], q1 = bp[1];
            const float bv[8] = {q0.x, q0.y, q0.z, q0.w, q1.x, q1.y, q1.z, q1.w};
            #pragma unroll
            for (int jj = 0; jj < 8; jj++) {
                acc[0][jj] = fmaf(a.x, bv[jj], acc[0][jj]);
                acc[1][jj] = fmaf(a.y, bv[jj], acc[1][jj]);
            }
        }
    }
    __syncthreads();
}

__global__ __launch_bounds__(256, 1) void head_kernel(
    const float* __restrict__ w1, const float* __restrict__ b1,
    const float* __restrict__ gg1, const float* __restrict__ be1,
    const float* __restrict__ w2, const float* __restrict__ b2,
    const float* __restrict__ gg2, const float* __restrict__ be2,
    const float* __restrict__ w3, const float* __restrict__ b3,
    const float* __restrict__ msz, float* __restrict__ out) {
    extern __shared__ float sm[];
    float* a0 = sm;                       // [c][r] 128 x LDH (32 rows used)
    float* a1 = sm + 128 * LDH;
    float* wbuf = a1 + 128 * LDH;
    float* ms = wbuf + 16 * 128;

    const int tid = threadIdx.x;
    const int tx = tid & 15, ty = tid >> 4;
    const int gp0 = blockIdx.x << 5;

    if (tid < 54) ms[tid] = msz[tid];
    for (int e = tid; e < 32 * 128; e += 256) {
        const int r = e & 31, c = e >> 5;
        a0[c * LDH + r] = g_feat[((size_t)(gp0 + r) << 7) + c];
    }

    float acc[2][8];
    const int j0 = tx << 3;
    #pragma unroll
    for (int i = 0; i < 2; i++)
        #pragma unroll
        for (int jj = 0; jj < 8; jj++) acc[i][jj] = 0.f;

    gemm_tile32(a0, w1, 128, 128, wbuf, acc, tid, tx, ty);
    #pragma unroll
    for (int jj = 0; jj < 8; jj++) {
        const float g = gg1[j0 + jj], bb = b1[j0 + jj], be = be1[j0 + jj];
        #pragma unroll
        for (int i = 0; i < 2; i++) {
            a1[(j0 + jj) * LDH + ty * 2 + i] =
                fminf(fmaxf(g * (acc[i][jj] + bb) + be, 0.f), 6.f);
            acc[i][jj] = 0.f;
        }
    }

    gemm_tile32(a1, w2, 128, 128, wbuf, acc, tid, tx, ty);
    #pragma unroll
    for (int jj = 0; jj < 8; jj++) {
        const float g = gg2[j0 + jj], bb = b2[j0 + jj], be = be2[j0 + jj];
        #pragma unroll
        for (int i = 0; i < 2; i++) {
            a0[(j0 + jj) * LDH + ty * 2 + i] =
                fminf(fmaxf(g * (acc[i][jj] + bb) + be, 0.f), 6.f);
            acc[i][jj] = 0.f;
        }
    }

    gemm_tile32(a0, w3, OUTCH, OUTCH, wbuf, acc, tid, tx, ty);
    {
        #pragma unroll
        for (int i = 0; i < 2; i++) {
            const int gp = gp0 + ty * 2 + i;
            #pragma unroll
            for (int jj = 0; jj < 8; jj++) {
                const int j = j0 + jj;
                if (j >= OUTCH) continue;
                const float v = acc[i][jj] + b3[j];
                if (j < 3) {
                    out[OFF_CENTER + gp * 3 + j] = g_newxyz[gp * 3 + j] + v;
                } else {
                    const int jr = j - 3;
                    if (jr < 2)        out[OFF_OBJ + gp * 2 + jr] = v;
                    else if (jr < 14)  out[OFF_HS + gp * 12 + (jr - 2)] = v;
                    else if (jr < 32)  out[OFF_SS + gp * 18 + (jr - 14)] = v;
                    else if (jr < 44) {
                        const int h = jr - 32;
                        out[OFF_HRN + gp * 12 + h] = v;
                        out[OFF_HR + gp * 12 + h] = v * 0.26179938779916667f;
                    } else if (jr < 98) {
                        const int t = jr - 44;
                        out[OFF_SRN + gp * 54 + t] = v;
                        out[OFF_SR + gp * 54 + t] = v * ms[t];
                    } else out[OFF_SEM + gp * 18 + (jr - 98)] = v;
                }
            }
        }
    }
}

__global__ __launch_bounds__(256) void tail_kernel(float* __restrict__ out) {
    const int i = blockIdx.x * blockDim.x + threadIdx.x;
    if (i < NBATCH * NPROP * 3) out[OFF_NEWXYZ + i] = g_newxyz[i];
    else if (i < NBATCH * NPROP * 4) {
        const int k = i - NBATCH * NPROP * 3;
        out[OFF_INDS + k] = (float)g_inds[k];
    }
}

extern "C" void kernel_launch(void* const* d_in, const int* in_sizes, int n_in,
                              void* d_out, int out_size) {
    const float* xyz   = (const float*)d_in[0];
    const float* feats = (const float*)d_in[1];
    const float* msz   = (const float*)d_in[2];
    const float* w_m0  = (const float*)d_in[3];
    const float* b_m0  = (const float*)d_in[4];
    const float* g_m0  = (const float*)d_in[5];
    const float* be_m0 = (const float*)d_in[6];
    const float* w_m1  = (const float*)d_in[7];
    const float* b_m1  = (const float*)d_in[8];
    const float* g_m1  = (const float*)d_in[9];
    const float* be_m1 = (const float*)d_in[10];
    const float* w_m2  = (const float*)d_in[11];
    const float* b_m2  = (const float*)d_in[12];
    const float* g_m2  = (const float*)d_in[13];
    const float* be_m2 = (const float*)d_in[14];
    const float* w1    = (const float*)d_in[15];
    const float* b1    = (const float*)d_in[16];
    const float* g1    = (const float*)d_in[17];
    const float* be1   = (const float*)d_in[18];
    const float* w2    = (const float*)d_in[19];
    const float* b2    = (const float*)d_in[20];
    const float* g2    = (const float*)d_in[21];
    const float* be2   = (const float*)d_in[22];
    const float* w3    = (const float*)d_in[23];
    const float* b3    = (const float*)d_in[24];
    float* out = (float*)d_out;

    cudaFuncSetAttribute(mlp_kernel, cudaFuncAttributeMaxDynamicSharedMemorySize, MLP_SMEM);
    cudaFuncSetAttribute(head_kernel, cudaFuncAttributeMaxDynamicSharedMemorySize, HEAD_SMEM);

    prepack_kernel<<<132, 256>>>(w_m0, w_m1, w_m2);
    fps_kernel<<<NBATCH, 1024>>>(xyz);
    ball_kernel<<<(NBATCH * NPROP * 32) / 256, 256>>>(xyz);
    mlp_kernel<<<NBATCH * NPROP / 4, 128, MLP_SMEM>>>(
        xyz, feats, b_m0, g_m0, be_m0, b_m1, g_m1, be_m1, b_m2, g_m2, be_m2);
    head_kernel<<<(NBATCH * NPROP) / 32, 256, HEAD_SMEM>>>(
        w1, b1, g1, be1, w2, b2, g2, be2, w3, b3, msz, out);
    tail_kernel<<<(NBATCH * NPROP * 4 + 255) / 256, 256>>>(out);
}

// round 7
// speedup vs baseline: 3.9999x; 1.3807x over previous
#include <cuda_runtime.h>
#include <cuda_bf16.h>
#include <cstdint>

#define NBATCH 32
#define NPTS   1024
#define NCH    256
#define NPROP  256
#define NSAMP  16
#define OUTCH  119

#define OFF_OBJ     0
#define OFF_CENTER  16384
#define OFF_HS      40960
#define OFF_HRN     139264
#define OFF_HR      237568
#define OFF_SS      335872
#define OFF_SRN     483328
#define OFF_SR      925696
#define OFF_SEM     1368064
#define OFF_NEWXYZ  1515520
#define OFF_INDS    1540096

#define KP0   272               // layer-0 MMA K (256 feats + 3 gxyz + pad), 17 chunks
#define LDA   280               // mlp A smem leading dim (bf16); 560B rows, conflict-free
#define LDH2  136               // head A smem leading dim (272B rows)
#define MLP_SMEM  (64 * LDA * 2 * 2)    // 71680 B
#define HEAD_SMEM (64 * LDH2 * 2 * 2)   // 34816 B

// ---------------- scratch ----------------
__device__ int   g_inds[NBATCH * NPROP];
__device__ float g_newxyz[NBATCH * NPROP * 3];
__device__ int   g_idx[NBATCH * NPROP * NSAMP];
__device__ float g_feat[NBATCH * NPROP * 128];
// B fragments in mma-lane order: u32 idx = ((c*NJ + j)*32 + lane)*2 + rr
__device__ __align__(16) uint32_t g_W0p[2][17 * 1024];
__device__ __align__(16) uint32_t g_W1p[2][8 * 1024];
__device__ __align__(16) uint32_t g_W2p[2][8 * 1024];
__device__ __align__(16) uint32_t g_H1p[2][8 * 1024];
__device__ __align__(16) uint32_t g_H2p[2][8 * 1024];
__device__ __align__(16) uint32_t g_H3p[2][8 * 960];     // NJ=15 (120 cols)

// ---------------- helpers ----------------
__device__ __forceinline__ uint32_t smem_u32(const void* p) {
    uint32_t a;
    asm("{ .reg .u64 t; cvta.to.shared.u64 t, %1; cvt.u32.u64 %0, t; }" : "=r"(a) : "l"(p));
    return a;
}
__device__ __forceinline__ uint32_t pack_bf2(float a, float b) {
    __nv_bfloat16 ha = __float2bfloat16(a), hb = __float2bfloat16(b);
    return (uint32_t)__bfloat16_as_ushort(ha) | ((uint32_t)__bfloat16_as_ushort(hb) << 16);
}
__device__ __forceinline__ uint32_t pack_lo2(float a, float b) {
    float ra = a - __bfloat162float(__float2bfloat16(a));
    float rb = b - __bfloat162float(__float2bfloat16(b));
    return pack_bf2(ra, rb);
}
__device__ __forceinline__ void ldsm4(uint32_t r[4], uint32_t addr) {
    asm volatile("ldmatrix.sync.aligned.m8n8.x4.shared.b16 {%0,%1,%2,%3}, [%4];"
                 : "=r"(r[0]), "=r"(r[1]), "=r"(r[2]), "=r"(r[3]) : "r"(addr));
}
__device__ __forceinline__ void mma16816(float d[4], const uint32_t a[4],
                                         uint32_t b0, uint32_t b1) {
    asm volatile("mma.sync.aligned.m16n8k16.row.col.f32.bf16.bf16.f32 "
                 "{%0,%1,%2,%3}, {%4,%5,%6,%7}, {%8,%9}, {%0,%1,%2,%3};"
                 : "+f"(d[0]), "+f"(d[1]), "+f"(d[2]), "+f"(d[3])
                 : "r"(a[0]), "r"(a[1]), "r"(a[2]), "r"(a[3]), "r"(b0), "r"(b1));
}

// generic warp GEMM: 16 rows x (NJ*8) cols, split-bf16 3-term
template <int NJ>
__device__ __forceinline__ void run_layer(float acc[16][4], uint32_t aH, uint32_t aL,
                                          const uint2* __restrict__ Wh,
                                          const uint2* __restrict__ Wl,
                                          int nchunk, int lane) {
    for (int kt = 0; kt < nchunk; kt++) {
        uint32_t ah[4], al[4];
        ldsm4(ah, aH + kt * 32);
        ldsm4(al, aL + kt * 32);
        uint2 bh[NJ], bl[NJ];
        #pragma unroll
        for (int j = 0; j < NJ; j++) bh[j] = __ldg(Wh + (kt * NJ + j) * 32 + lane);
        #pragma unroll
        for (int j = 0; j < NJ; j++) bl[j] = __ldg(Wl + (kt * NJ + j) * 32 + lane);
        #pragma unroll
        for (int j = 0; j < NJ; j++) {
            mma16816(acc[j], ah, bh[j].x, bh[j].y);
            mma16816(acc[j], al, bh[j].x, bh[j].y);
            mma16816(acc[j], ah, bl[j].x, bl[j].y);
        }
    }
}

// BN + relu(/relu6) epilogue -> write back as next A (hi/lo), zero acc
template <bool CLIP>
__device__ __forceinline__ void epi_generic(float acc[16][4], __nv_bfloat16* Ah,
                                            __nv_bfloat16* Al,
                                            const float* __restrict__ bb,
                                            const float* __restrict__ gg,
                                            const float* __restrict__ be,
                                            int w, int lane, int lda) {
    const int g = lane >> 2, t = lane & 3;
    const int rA = w * 16 + g, rB = rA + 8;
    #pragma unroll
    for (int j = 0; j < 16; j++) {
        const int n0 = j * 8 + t * 2, n1 = n0 + 1;
        const float g0 = __ldg(gg + n0), g1 = __ldg(gg + n1);
        const float c0 = __ldg(bb + n0), c1 = __ldg(bb + n1);
        const float e0 = __ldg(be + n0), e1 = __ldg(be + n1);
        float v00 = fmaxf(g0 * (acc[j][0] + c0) + e0, 0.f);
        float v01 = fmaxf(g1 * (acc[j][1] + c1) + e1, 0.f);
        float v10 = fmaxf(g0 * (acc[j][2] + c0) + e0, 0.f);
        float v11 = fmaxf(g1 * (acc[j][3] + c1) + e1, 0.f);
        if (CLIP) {
            v00 = fminf(v00, 6.f); v01 = fminf(v01, 6.f);
            v10 = fminf(v10, 6.f); v11 = fminf(v11, 6.f);
        }
        *(uint32_t*)(Ah + rA * lda + n0) = pack_bf2(v00, v01);
        *(uint32_t*)(Ah + rB * lda + n0) = pack_bf2(v10, v11);
        *(uint32_t*)(Al + rA * lda + n0) = pack_lo2(v00, v01);
        *(uint32_t*)(Al + rB * lda + n0) = pack_lo2(v10, v11);
        acc[j][0] = acc[j][1] = acc[j][2] = acc[j][3] = 0.f;
    }
    __syncwarp();
}

// ---------------- prepack: all weights -> lane-order B fragments ----------------
__device__ __forceinline__ float w0v(const float* __restrict__ w0, int k, int n) {
    if (k < 256) return w0[(3 + k) * 128 + n];
    if (k < 259) return w0[(k - 256) * 128 + n];
    return 0.f;
}
__device__ __forceinline__ void pack_frag16(uint32_t* hi, uint32_t* lo, int idx,
                                            float v0, float v1) {
    hi[idx] = pack_bf2(v0, v1);
    lo[idx] = pack_lo2(v0, v1);
}
__global__ __launch_bounds__(256) void prepack_kernel(
    const float* __restrict__ w0, const float* __restrict__ w1,
    const float* __restrict__ w2, const float* __restrict__ h1,
    const float* __restrict__ h2, const float* __restrict__ h3) {
    const int nth = gridDim.x * blockDim.x;
    const int s0 = 17 * 1024, s1 = s0 + 8192, s2 = s1 + 8192;
    const int s3 = s2 + 8192, s4 = s3 + 8192, s5 = s4 + 8 * 960;
    for (int t = blockIdx.x * blockDim.x + threadIdx.x; t < s5; t += nth) {
        if (t < s4) {
            // NJ=16 segments
            int idx, which;
            if (t < s0) { idx = t; which = 0; }
            else if (t < s1) { idx = t - s0; which = 1; }
            else if (t < s2) { idx = t - s1; which = 2; }
            else if (t < s3) { idx = t - s2; which = 3; }
            else { idx = t - s3; which = 4; }
            const int c = idx >> 10, j = (idx >> 6) & 15, lane = (idx >> 1) & 31, rr = idx & 1;
            const int k0 = c * 16 + (lane & 3) * 2 + rr * 8;
            const int n = j * 8 + (lane >> 2);
            float v0, v1;
            if (which == 0) { v0 = w0v(w0, k0, n); v1 = w0v(w0, k0 + 1, n); }
            else {
                const float* w = (which == 1) ? w1 : (which == 2) ? w2 : (which == 3) ? h1 : h2;
                v0 = w[k0 * 128 + n]; v1 = w[(k0 + 1) * 128 + n];
            }
            switch (which) {
                case 0: pack_frag16(g_W0p[0], g_W0p[1], idx, v0, v1); break;
                case 1: pack_frag16(g_W1p[0], g_W1p[1], idx, v0, v1); break;
                case 2: pack_frag16(g_W2p[0], g_W2p[1], idx, v0, v1); break;
                case 3: pack_frag16(g_H1p[0], g_H1p[1], idx, v0, v1); break;
                default: pack_frag16(g_H2p[0], g_H2p[1], idx, v0, v1); break;
            }
        } else {
            // h3: NJ=15, N=119 (cols >=119 zero)
            const int idx = t - s4;
            const int c = idx / 960, rem = idx % 960;
            const int j = rem >> 6, lane = (rem >> 1) & 31, rr = rem & 1;
            const int k0 = c * 16 + (lane & 3) * 2 + rr * 8;
            const int n = j * 8 + (lane >> 2);
            const float v0 = (n < OUTCH) ? h3[k0 * OUTCH + n] : 0.f;
            const float v1 = (n < OUTCH) ? h3[(k0 + 1) * OUTCH + n] : 0.f;
            pack_frag16(g_H3p[0], g_H3p[1], idx, v0, v1);
        }
    }
}

// ---------------- FPS: 256 thr, 4 pts/thread, ONE barrier per iter ----------------
__global__ __launch_bounds__(256) void fps_kernel(const float* __restrict__ xyz) {
    __shared__ float px[NPTS], py[NPTS], pz[NPTS];
    __shared__ float wv[2][8];
    __shared__ int   wi[2][8];
    const int b = blockIdx.x, tid = threadIdx.x;
    const int w = tid >> 5, lane = tid & 31;
    const float* xb = xyz + (size_t)b * NPTS * 3;

    for (int i = tid; i < NPTS; i += 256) {
        px[i] = xb[i * 3 + 0];
        py[i] = xb[i * 3 + 1];
        pz[i] = xb[i * 3 + 2];
    }
    __syncthreads();

    float x[4], y[4], z[4], dd[4];
    #pragma unroll
    for (int i = 0; i < 4; i++) {
        const int idx = tid + 256 * i;
        x[i] = px[idx]; y[i] = py[idx]; z[i] = pz[idx];
        dd[i] = 1e10f;
    }
    float bx = px[0], by = py[0], bz = pz[0];
    if (tid == 0) {
        g_inds[b * NPROP] = 0;
        g_newxyz[b * NPROP * 3 + 0] = bx;
        g_newxyz[b * NPROP * 3 + 1] = by;
        g_newxyz[b * NPROP * 3 + 2] = bz;
    }
    int par = 0;
    for (int it = 1; it < NPROP; it++) {
        float best = -1.f;
        int bid = 0;
        #pragma unroll
        for (int i = 0; i < 4; i++) {
            const float dx = x[i] - bx, dy = y[i] - by, dz = z[i] - bz;
            const float d = __fadd_rn(__fadd_rn(__fmul_rn(dx, dx), __fmul_rn(dy, dy)),
                                      __fmul_rn(dz, dz));
            dd[i] = fminf(dd[i], d);
            if (dd[i] > best) { best = dd[i]; bid = tid + 256 * i; }
        }
        #pragma unroll
        for (int o = 16; o; o >>= 1) {
            const float v2 = __shfl_xor_sync(0xffffffffu, best, o);
            const int   i2 = __shfl_xor_sync(0xffffffffu, bid, o);
            if (v2 > best || (v2 == best && i2 < bid)) { best = v2; bid = i2; }
        }
        if (lane == 0) { wv[par][w] = best; wi[par][w] = bid; }
        __syncthreads();
        float v = wv[par][0];
        int id = wi[par][0];
        #pragma unroll
        for (int k = 1; k < 8; k++) {
            const float vk = wv[par][k];
            const int ik = wi[par][k];
            if (vk > v || (vk == v && ik < id)) { v = vk; id = ik; }
        }
        bx = px[id]; by = py[id]; bz = pz[id];
        if (tid == 0) {
            g_inds[b * NPROP + it] = id;
            g_newxyz[(b * NPROP + it) * 3 + 0] = bx;
            g_newxyz[(b * NPROP + it) * 3 + 1] = by;
            g_newxyz[(b * NPROP + it) * 3 + 2] = bz;
        }
        par ^= 1;
    }
}

// ---------------- Ball query (verified) ----------------
__global__ __launch_bounds__(256) void ball_kernel(const float* __restrict__ xyz) {
    const int gw = (blockIdx.x * blockDim.x + threadIdx.x) >> 5;
    const int lane = threadIdx.x & 31;
    const int b = gw >> 8;
    const float cx = g_newxyz[gw * 3], cy = g_newxyz[gw * 3 + 1], cz = g_newxyz[gw * 3 + 2];
    const float* xb = xyz + (size_t)b * NPTS * 3;
    int cnt = 0, buf[NSAMP];
    for (int c0 = 0; c0 < NPTS; c0 += 32) {
        const int j = c0 + lane;
        float dx = xb[j * 3] - cx, dy = xb[j * 3 + 1] - cy, dz = xb[j * 3 + 2] - cz;
        float d = __fadd_rn(__fadd_rn(__fmul_rn(dx, dx), __fmul_rn(dy, dy)), __fmul_rn(dz, dz));
        unsigned m = __ballot_sync(0xffffffffu, d < 0.09f);
        if (lane == 0) {
            while (m && cnt < NSAMP) { int t = __ffs(m) - 1; buf[cnt++] = c0 + t; m &= m - 1; }
        }
        cnt = __shfl_sync(0xffffffffu, cnt, 0);
        if (cnt >= NSAMP) break;
    }
    if (lane == 0) {
        const int f = (cnt > 0) ? buf[0] : (NPTS - 1);
        for (int s = cnt; s < NSAMP; s++) buf[s] = f;
        for (int s = 0; s < NSAMP; s++) g_idx[gw * NSAMP + s] = buf[s];
    }
}

// ---------------- mma MLP (verified R5 structure) ----------------
__global__ __launch_bounds__(128, 3) void mlp_kernel(
    const float* __restrict__ xyz, const float* __restrict__ feats,
    const float* __restrict__ b0, const float* __restrict__ gg0, const float* __restrict__ be0,
    const float* __restrict__ b1, const float* __restrict__ gg1, const float* __restrict__ be1,
    const float* __restrict__ b2, const float* __restrict__ gg2, const float* __restrict__ be2) {
    extern __shared__ __align__(16) char dsm[];
    __nv_bfloat16* Ah = (__nv_bfloat16*)dsm;
    __nv_bfloat16* Al = Ah + 64 * LDA;

    const int tid = threadIdx.x, w = tid >> 5, lane = tid & 31;
    const int p = blockIdx.x * 4 + w;
    const int b = p >> 8;

    int jloc = (lane < 16) ? g_idx[p * NSAMP + lane] : 0;
    const float* fb = feats + (size_t)b * NPTS * NCH;
    #pragma unroll 1
    for (int s = 0; s < 16; s++) {
        const int j = __shfl_sync(0xffffffffu, jloc, s);
        const int row = w * 16 + s;
        const float4* src = (const float4*)(fb + (size_t)j * NCH);
        float4 f0 = src[lane * 2], f1 = src[lane * 2 + 1];
        uint4 H, L;
        H.x = pack_bf2(f0.x, f0.y); H.y = pack_bf2(f0.z, f0.w);
        H.z = pack_bf2(f1.x, f1.y); H.w = pack_bf2(f1.z, f1.w);
        L.x = pack_lo2(f0.x, f0.y); L.y = pack_lo2(f0.z, f0.w);
        L.z = pack_lo2(f1.x, f1.y); L.w = pack_lo2(f1.z, f1.w);
        *(uint4*)(Ah + row * LDA + lane * 8) = H;
        *(uint4*)(Al + row * LDA + lane * 8) = L;
    }
    if (lane < 16) {
        const int row = w * 16 + lane;
        const float* np = g_newxyz + p * 3;
        const float* xp = xyz + ((size_t)b * NPTS + jloc) * 3;
        #pragma unroll
        for (int c = 0; c < 3; c++) {
            const float v = __fdiv_rn(xp[c] - np[c], 0.3f);
            __nv_bfloat16 h = __float2bfloat16(v);
            Ah[row * LDA + 256 + c] = h;
            Al[row * LDA + 256 + c] = __float2bfloat16(v - __bfloat162float(h));
        }
        for (int c = 259; c < KP0; c++) {
            Ah[row * LDA + c] = __float2bfloat16(0.f);
            Al[row * LDA + c] = __float2bfloat16(0.f);
        }
    }
    __syncwarp();

    float acc[16][4];
    #pragma unroll
    for (int j = 0; j < 16; j++)
        acc[j][0] = acc[j][1] = acc[j][2] = acc[j][3] = 0.f;

    const uint32_t aOff = ((w * 16 + (lane & 15)) * LDA + (lane >> 4) * 8) * 2;
    const uint32_t aH = smem_u32(Ah) + aOff;
    const uint32_t aL = smem_u32(Al) + aOff;

    run_layer<16>(acc, aH, aL, (const uint2*)g_W0p[0], (const uint2*)g_W0p[1], 17, lane);
    epi_generic<false>(acc, Ah, Al, b0, gg0, be0, w, lane, LDA);
    run_layer<16>(acc, aH, aL, (const uint2*)g_W1p[0], (const uint2*)g_W1p[1], 8, lane);
    epi_generic<false>(acc, Ah, Al, b1, gg1, be1, w, lane, LDA);
    run_layer<16>(acc, aH, aL, (const uint2*)g_W2p[0], (const uint2*)g_W2p[1], 8, lane);

    {
        const int t = lane & 3;
        #pragma unroll
        for (int j = 0; j < 16; j++) {
            const int n0 = j * 8 + t * 2, n1 = n0 + 1;
            const float g0 = __ldg(gg2 + n0), g1 = __ldg(gg2 + n1);
            const float c0 = __ldg(b2 + n0), c1 = __ldg(b2 + n1);
            const float e0 = __ldg(be2 + n0), e1 = __ldg(be2 + n1);
            float m0 = fmaxf(fmaxf(g0 * (acc[j][0] + c0) + e0, 0.f),
                             fmaxf(g0 * (acc[j][2] + c0) + e0, 0.f));
            float m1 = fmaxf(fmaxf(g1 * (acc[j][1] + c1) + e1, 0.f),
                             fmaxf(g1 * (acc[j][3] + c1) + e1, 0.f));
            #pragma unroll
            for (int o = 4; o <= 16; o <<= 1) {
                m0 = fmaxf(m0, __shfl_xor_sync(0xffffffffu, m0, o));
                m1 = fmaxf(m1, __shfl_xor_sync(0xffffffffu, m1, o));
            }
            if (lane < 4)
                *(float2*)(g_feat + ((size_t)p << 7) + n0) = make_float2(m0, m1);
        }
    }
}

// ---------------- mma head: warp = 16 proposals ----------------
__device__ __forceinline__ void scatter_out(float* __restrict__ out, int gp, int n,
                                            float v, const float* __restrict__ msz) {
    if (n >= OUTCH) return;
    if (n < 3) {
        out[OFF_CENTER + gp * 3 + n] = g_newxyz[gp * 3 + n] + v;
        return;
    }
    const int jr = n - 3;
    if (jr < 2)       out[OFF_OBJ + gp * 2 + jr] = v;
    else if (jr < 14) out[OFF_HS + gp * 12 + (jr - 2)] = v;
    else if (jr < 32) out[OFF_SS + gp * 18 + (jr - 14)] = v;
    else if (jr < 44) {
        const int h = jr - 32;
        out[OFF_HRN + gp * 12 + h] = v;
        out[OFF_HR + gp * 12 + h] = v * 0.26179938779916667f;
    } else if (jr < 98) {
        const int t = jr - 44;
        out[OFF_SRN + gp * 54 + t] = v;
        out[OFF_SR + gp * 54 + t] = v * __ldg(msz + t);
    } else out[OFF_SEM + gp * 18 + (jr - 98)] = v;
}

__global__ __launch_bounds__(128, 3) void head_kernel(
    const float* __restrict__ b1, const float* __restrict__ gg1, const float* __restrict__ be1,
    const float* __restrict__ b2, const float* __restrict__ gg2, const float* __restrict__ be2,
    const float* __restrict__ b3, const float* __restrict__ msz, float* __restrict__ out) {
    extern __shared__ __align__(16) char dsm[];
    __nv_bfloat16* Ah = (__nv_bfloat16*)dsm;        // 64 x LDH2
    __nv_bfloat16* Al = Ah + 64 * LDH2;

    const int tid = threadIdx.x, w = tid >> 5, lane = tid & 31;
    const int gp0 = blockIdx.x * 64;

    // load A (warp-private 16 rows of g_feat, fp32 -> hi/lo)
    #pragma unroll 1
    for (int r = 0; r < 16; r++) {
        const int row = w * 16 + r;
        const float4 f = ((const float4*)(g_feat + ((size_t)(gp0 + row) << 7)))[lane];
        uint2 H, L;
        H.x = pack_bf2(f.x, f.y); H.y = pack_bf2(f.z, f.w);
        L.x = pack_lo2(f.x, f.y); L.y = pack_lo2(f.z, f.w);
        *(uint2*)(Ah + row * LDH2 + lane * 4) = H;
        *(uint2*)(Al + row * LDH2 + lane * 4) = L;
    }
    __syncwarp();

    float acc[16][4];
    #pragma unroll
    for (int j = 0; j < 16; j++)
        acc[j][0] = acc[j][1] = acc[j][2] = acc[j][3] = 0.f;

    const uint32_t aOff = ((w * 16 + (lane & 15)) * LDH2 + (lane >> 4) * 8) * 2;
    const uint32_t aH = smem_u32(Ah) + aOff;
    const uint32_t aL = smem_u32(Al) + aOff;

    run_layer<16>(acc, aH, aL, (const uint2*)g_H1p[0], (const uint2*)g_H1p[1], 8, lane);
    epi_generic<true>(acc, Ah, Al, b1, gg1, be1, w, lane, LDH2);
    run_layer<16>(acc, aH, aL, (const uint2*)g_H2p[0], (const uint2*)g_H2p[1], 8, lane);
    epi_generic<true>(acc, Ah, Al, b2, gg2, be2, w, lane, LDH2);
    run_layer<15>(acc, aH, aL, (const uint2*)g_H3p[0], (const uint2*)g_H3p[1], 8, lane);

    // scatter epilogue
    {
        const int g = lane >> 2, t = lane & 3;
        const int gpA = gp0 + w * 16 + g, gpB = gpA + 8;
        #pragma unroll
        for (int j = 0; j < 15; j++) {
            const int n0 = j * 8 + t * 2, n1 = n0 + 1;
            const float bb0 = (n0 < OUTCH) ? __ldg(b3 + n0) : 0.f;
            const float bb1 = (n1 < OUTCH) ? __ldg(b3 + n1) : 0.f;
            scatter_out(out, gpA, n0, acc[j][0] + bb0, msz);
            scatter_out(out, gpA, n1, acc[j][1] + bb1, msz);
            scatter_out(out, gpB, n0, acc[j][2] + bb0, msz);
            scatter_out(out, gpB, n1, acc[j][3] + bb1, msz);
        }
    }
}

__global__ __launch_bounds__(256) void tail_kernel(float* __restrict__ out) {
    const int i = blockIdx.x * blockDim.x + threadIdx.x;
    if (i < NBATCH * NPROP * 3) out[OFF_NEWXYZ + i] = g_newxyz[i];
    else if (i < NBATCH * NPROP * 4) {
        const int k = i - NBATCH * NPROP * 3;
        out[OFF_INDS + k] = (float)g_inds[k];
    }
}

extern "C" void kernel_launch(void* const* d_in, const int* in_sizes, int n_in,
                              void* d_out, int out_size) {
    const float* xyz   = (const float*)d_in[0];
    const float* feats = (const float*)d_in[1];
    const float* msz   = (const float*)d_in[2];
    const float* w_m0  = (const float*)d_in[3];
    const float* b_m0  = (const float*)d_in[4];
    const float* g_m0  = (const float*)d_in[5];
    const float* be_m0 = (const float*)d_in[6];
    const float* w_m1  = (const float*)d_in[7];
    const float* b_m1  = (const float*)d_in[8];
    const float* g_m1  = (const float*)d_in[9];
    const float* be_m1 = (const float*)d_in[10];
    const float* w_m2  = (const float*)d_in[11];
    const float* b_m2  = (const float*)d_in[12];
    const float* g_m2  = (const float*)d_in[13];
    const float* be_m2 = (const float*)d_in[14];
    const float* w1    = (const float*)d_in[15];
    const float* b1    = (const float*)d_in[16];
    const float* g1    = (const float*)d_in[17];
    const float* be1   = (const float*)d_in[18];
    const float* w2    = (const float*)d_in[19];
    const float* b2    = (const float*)d_in[20];
    const float* g2    = (const float*)d_in[21];
    const float* be2   = (const float*)d_in[22];
    const float* w3    = (const float*)d_in[23];
    const float* b3    = (const float*)d_in[24];
    float* out = (float*)d_out;

    cudaFuncSetAttribute(mlp_kernel, cudaFuncAttributeMaxDynamicSharedMemorySize, MLP_SMEM);
    cudaFuncSetAttribute(head_kernel, cudaFuncAttributeMaxDynamicSharedMemorySize, HEAD_SMEM);

    prepack_kernel<<<227, 256>>>(w_m0, w_m1, w_m2, w1, w2, w3);
    fps_kernel<<<NBATCH, 256>>>(xyz);
    ball_kernel<<<(NBATCH * NPROP * 32) / 256, 256>>>(xyz);
    mlp_kernel<<<NBATCH * NPROP / 4, 128, MLP_SMEM>>>(
        xyz, feats, b_m0, g_m0, be_m0, b_m1, g_m1, be_m1, b_m2, g_m2, be_m2);
    head_kernel<<<(NBATCH * NPROP) / 64, 128, HEAD_SMEM>>>(
        b1, g1, be1, b2, g2, be2, b3, msz, out);
    tail_kernel<<<(NBATCH * NPROP * 4 + 255) / 256, 256>>>(out);
}

// round 9
// speedup vs baseline: 4.1864x; 1.0466x over previous
#include <cuda_runtime.h>
#include <cuda_bf16.h>
#include <cstdint>

#define NBATCH 32
#define NPTS   1024
#define NCH    256
#define NPROP  256
#define NSAMP  16
#define OUTCH  119

#define OFF_OBJ     0
#define OFF_CENTER  16384
#define OFF_HS      40960
#define OFF_HRN     139264
#define OFF_HR      237568
#define OFF_SS      335872
#define OFF_SRN     483328
#define OFF_SR      925696
#define OFF_SEM     1368064
#define OFF_NEWXYZ  1515520
#define OFF_INDS    1540096

#define LDB   136               // A smem leading dim (bf16), 272B rows, conflict-free
#define MLP_SMEM  (64 * LDB * 2 * 2)    // 34816 B (layers 1-2 A only)
#define HEAD_SMEM (64 * LDB * 2 * 2)    // 34816 B

// ---------------- scratch ----------------
__device__ int   g_inds[NBATCH * NPROP];
__device__ float g_newxyz[NBATCH * NPROP * 3];
__device__ int   g_idx[NBATCH * NPROP * NSAMP];
__device__ float g_feat[NBATCH * NPROP * 128];
// B fragments in mma-lane order: u32 idx = ((c*NJ + j)*32 + lane)*2 + rr
__device__ __align__(16) uint32_t g_W0p[2][17 * 1024];
__device__ __align__(16) uint32_t g_W1p[2][8 * 1024];
__device__ __align__(16) uint32_t g_W2p[2][8 * 1024];
__device__ __align__(16) uint32_t g_H1p[2][8 * 1024];
__device__ __align__(16) uint32_t g_H2p[2][8 * 1024];
__device__ __align__(16) uint32_t g_H3p[2][8 * 960];     // NJ=15

// ---------------- helpers ----------------
__device__ __forceinline__ uint32_t smem_u32(const void* p) {
    uint32_t a;
    asm("{ .reg .u64 t; cvta.to.shared.u64 t, %1; cvt.u32.u64 %0, t; }" : "=r"(a) : "l"(p));
    return a;
}
__device__ __forceinline__ uint32_t pack_bf2(float a, float b) {
    __nv_bfloat16 ha = __float2bfloat16(a), hb = __float2bfloat16(b);
    return (uint32_t)__bfloat16_as_ushort(ha) | ((uint32_t)__bfloat16_as_ushort(hb) << 16);
}
__device__ __forceinline__ uint32_t pack_lo2(float a, float b) {
    float ra = a - __bfloat162float(__float2bfloat16(a));
    float rb = b - __bfloat162float(__float2bfloat16(b));
    return pack_bf2(ra, rb);
}
__device__ __forceinline__ void ldsm4(uint32_t r[4], uint32_t addr) {
    asm volatile("ldmatrix.sync.aligned.m8n8.x4.shared.b16 {%0,%1,%2,%3}, [%4];"
                 : "=r"(r[0]), "=r"(r[1]), "=r"(r[2]), "=r"(r[3]) : "r"(addr));
}
__device__ __forceinline__ void mma16816(float d[4], const uint32_t a[4],
                                         uint32_t b0, uint32_t b1) {
    asm volatile("mma.sync.aligned.m16n8k16.row.col.f32.bf16.bf16.f32 "
                 "{%0,%1,%2,%3}, {%4,%5,%6,%7}, {%8,%9}, {%0,%1,%2,%3};"
                 : "+f"(d[0]), "+f"(d[1]), "+f"(d[2]), "+f"(d[3])
                 : "r"(a[0]), "r"(a[1]), "r"(a[2]), "r"(a[3]), "r"(b0), "r"(b1));
}

// 3-term split mma over one K-chunk for NJ j-tiles, B loads in groups of 8
template <int NJ>
__device__ __forceinline__ void chunk_mma(float acc[NJ][4], const uint32_t ah[4],
                                          const uint32_t al[4],
                                          const uint2* __restrict__ Wh,
                                          const uint2* __restrict__ Wl,
                                          int kt, int lane) {
    for (int j0 = 0; j0 < NJ; j0 += 8) {
        uint2 bh[8], bl[8];
        #pragma unroll
        for (int q = 0; q < 8; q++)
            if (j0 + q < NJ) bh[q] = __ldg(Wh + (kt * NJ + j0 + q) * 32 + lane);
        #pragma unroll
        for (int q = 0; q < 8; q++)
            if (j0 + q < NJ) bl[q] = __ldg(Wl + (kt * NJ + j0 + q) * 32 + lane);
        #pragma unroll
        for (int q = 0; q < 8; q++) {
            if (j0 + q < NJ) {
                mma16816(acc[j0 + q], ah, bh[q].x, bh[q].y);
                mma16816(acc[j0 + q], al, bh[q].x, bh[q].y);
                mma16816(acc[j0 + q], ah, bl[q].x, bl[q].y);
            }
        }
    }
}

template <int NJ>
__device__ __forceinline__ void run_layer_sm(float acc[NJ][4], uint32_t aH, uint32_t aL,
                                             const uint2* __restrict__ Wh,
                                             const uint2* __restrict__ Wl,
                                             int nchunk, int lane) {
    for (int kt = 0; kt < nchunk; kt++) {
        uint32_t ah[4], al[4];
        ldsm4(ah, aH + kt * 32);
        ldsm4(al, aL + kt * 32);
        chunk_mma<NJ>(acc, ah, al, Wh, Wl, kt, lane);
    }
}

// BN + relu(/relu6) epilogue -> write back as next A (hi/lo), zero acc
template <bool CLIP>
__device__ __forceinline__ void epi_generic(float acc[16][4], __nv_bfloat16* Ah,
                                            __nv_bfloat16* Al,
                                            const float* __restrict__ bb,
                                            const float* __restrict__ gg,
                                            const float* __restrict__ be,
                                            int w, int lane) {
    const int g = lane >> 2, t = lane & 3;
    const int rA = w * 16 + g, rB = rA + 8;
    #pragma unroll
    for (int j = 0; j < 16; j++) {
        const int n0 = j * 8 + t * 2, n1 = n0 + 1;
        const float g0 = __ldg(gg + n0), g1 = __ldg(gg + n1);
        const float c0 = __ldg(bb + n0), c1 = __ldg(bb + n1);
        const float e0 = __ldg(be + n0), e1 = __ldg(be + n1);
        float v00 = fmaxf(g0 * (acc[j][0] + c0) + e0, 0.f);
        float v01 = fmaxf(g1 * (acc[j][1] + c1) + e1, 0.f);
        float v10 = fmaxf(g0 * (acc[j][2] + c0) + e0, 0.f);
        float v11 = fmaxf(g1 * (acc[j][3] + c1) + e1, 0.f);
        if (CLIP) {
            v00 = fminf(v00, 6.f); v01 = fminf(v01, 6.f);
            v10 = fminf(v10, 6.f); v11 = fminf(v11, 6.f);
        }
        *(uint32_t*)(Ah + rA * LDB + n0) = pack_bf2(v00, v01);
        *(uint32_t*)(Ah + rB * LDB + n0) = pack_bf2(v10, v11);
        *(uint32_t*)(Al + rA * LDB + n0) = pack_lo2(v00, v01);
        *(uint32_t*)(Al + rB * LDB + n0) = pack_lo2(v10, v11);
        acc[j][0] = acc[j][1] = acc[j][2] = acc[j][3] = 0.f;
    }
    __syncwarp();
}

// ---------------- combined FPS + prepack ----------------
__device__ __forceinline__ float w0v(const float* __restrict__ w0, int k, int n) {
    if (k < 256) return w0[(3 + k) * 128 + n];
    if (k < 259) return w0[(k - 256) * 128 + n];
    return 0.f;
}
__device__ __forceinline__ void pack_frag16(uint32_t* hi, uint32_t* lo, int idx,
                                            float v0, float v1) {
    hi[idx] = pack_bf2(v0, v1);
    lo[idx] = pack_lo2(v0, v1);
}

__global__ __launch_bounds__(256) void pre_kernel(
    const float* __restrict__ xyz,
    const float* __restrict__ w0, const float* __restrict__ w1,
    const float* __restrict__ w2, const float* __restrict__ h1,
    const float* __restrict__ h2, const float* __restrict__ h3) {
    __shared__ float px[NPTS], py[NPTS], pz[NPTS];
    __shared__ float wv[2][8];
    __shared__ int   wi[2][8];
    const int tid = threadIdx.x;

    if (blockIdx.x >= 32) {
        // -------- prepack path --------
        const int s0 = 17 * 1024, s1 = s0 + 8192, s2 = s1 + 8192;
        const int s3 = s2 + 8192, s4 = s3 + 8192, s5 = s4 + 8 * 960;
        const int t = (blockIdx.x - 32) * 256 + tid;
        if (t >= s5) return;
        if (t < s4) {
            int idx, which;
            if (t < s0) { idx = t; which = 0; }
            else if (t < s1) { idx = t - s0; which = 1; }
            else if (t < s2) { idx = t - s1; which = 2; }
            else if (t < s3) { idx = t - s2; which = 3; }
            else { idx = t - s3; which = 4; }
            const int c = idx >> 10, j = (idx >> 6) & 15, lane = (idx >> 1) & 31, rr = idx & 1;
            const int k0 = c * 16 + (lane & 3) * 2 + rr * 8;
            const int n = j * 8 + (lane >> 2);
            float v0, v1;
            if (which == 0) { v0 = w0v(w0, k0, n); v1 = w0v(w0, k0 + 1, n); }
            else {
                const float* w = (which == 1) ? w1 : (which == 2) ? w2 : (which == 3) ? h1 : h2;
                v0 = w[k0 * 128 + n]; v1 = w[(k0 + 1) * 128 + n];
            }
            switch (which) {
                case 0: pack_frag16(g_W0p[0], g_W0p[1], idx, v0, v1); break;
                case 1: pack_frag16(g_W1p[0], g_W1p[1], idx, v0, v1); break;
                case 2: pack_frag16(g_W2p[0], g_W2p[1], idx, v0, v1); break;
                case 3: pack_frag16(g_H1p[0], g_H1p[1], idx, v0, v1); break;
                default: pack_frag16(g_H2p[0], g_H2p[1], idx, v0, v1); break;
            }
        } else {
            const int idx = t - s4;
            const int c = idx / 960, rem = idx % 960;
            const int j = rem >> 6, lane = (rem >> 1) & 31, rr = rem & 1;
            const int k0 = c * 16 + (lane & 3) * 2 + rr * 8;
            const int n = j * 8 + (lane >> 2);
            const float v0 = (n < OUTCH) ? h3[k0 * OUTCH + n] : 0.f;
            const float v1 = (n < OUTCH) ? h3[(k0 + 1) * OUTCH + n] : 0.f;
            pack_frag16(g_H3p[0], g_H3p[1], idx, v0, v1);
        }
        return;
    }

    // -------- FPS path (verified) --------
    const int b = blockIdx.x;
    const int w = tid >> 5, lane = tid & 31;
    const float* xb = xyz + (size_t)b * NPTS * 3;

    for (int i = tid; i < NPTS; i += 256) {
        px[i] = xb[i * 3 + 0];
        py[i] = xb[i * 3 + 1];
        pz[i] = xb[i * 3 + 2];
    }
    __syncthreads();

    float x[4], y[4], z[4], dd[4];
    #pragma unroll
    for (int i = 0; i < 4; i++) {
        const int idx = tid + 256 * i;
        x[i] = px[idx]; y[i] = py[idx]; z[i] = pz[idx];
        dd[i] = 1e10f;
    }
    float bx = px[0], by = py[0], bz = pz[0];
    if (tid == 0) {
        g_inds[b * NPROP] = 0;
        g_newxyz[b * NPROP * 3 + 0] = bx;
        g_newxyz[b * NPROP * 3 + 1] = by;
        g_newxyz[b * NPROP * 3 + 2] = bz;
    }
    int par = 0;
    for (int it = 1; it < NPROP; it++) {
        float best = -1.f;
        int bid = 0;
        #pragma unroll
        for (int i = 0; i < 4; i++) {
            const float dx = x[i] - bx, dy = y[i] - by, dz = z[i] - bz;
            const float d = __fadd_rn(__fadd_rn(__fmul_rn(dx, dx), __fmul_rn(dy, dy)),
                                      __fmul_rn(dz, dz));
            dd[i] = fminf(dd[i], d);
            if (dd[i] > best) { best = dd[i]; bid = tid + 256 * i; }
        }
        #pragma unroll
        for (int o = 16; o; o >>= 1) {
            const float v2 = __shfl_xor_sync(0xffffffffu, best, o);
            const int   i2 = __shfl_xor_sync(0xffffffffu, bid, o);
            if (v2 > best || (v2 == best && i2 < bid)) { best = v2; bid = i2; }
        }
        if (lane == 0) { wv[par][w] = best; wi[par][w] = bid; }
        __syncthreads();
        float v = wv[par][0];
        int id = wi[par][0];
        #pragma unroll
        for (int k = 1; k < 8; k++) {
            const float vk = wv[par][k];
            const int ik = wi[par][k];
            if (vk > v || (vk == v && ik < id)) { v = vk; id = ik; }
        }
        bx = px[id]; by = py[id]; bz = pz[id];
        if (tid == 0) {
            g_inds[b * NPROP + it] = id;
            g_newxyz[(b * NPROP + it) * 3 + 0] = bx;
            g_newxyz[(b * NPROP + it) * 3 + 1] = by;
            g_newxyz[(b * NPROP + it) * 3 + 2] = bz;
        }
        par ^= 1;
    }
}

// ---------------- Ball query + tail (verified parts) ----------------
__global__ __launch_bounds__(256) void ball_kernel(const float* __restrict__ xyz,
                                                   float* __restrict__ out) {
    const int gw = (blockIdx.x * blockDim.x + threadIdx.x) >> 5;
    const int lane = threadIdx.x & 31;
    const int b = gw >> 8;
    const float cx = g_newxyz[gw * 3], cy = g_newxyz[gw * 3 + 1], cz = g_newxyz[gw * 3 + 2];
    const float* xb = xyz + (size_t)b * NPTS * 3;
    int cnt = 0, buf[NSAMP];
    for (int c0 = 0; c0 < NPTS; c0 += 32) {
        const int j = c0 + lane;
        float dx = xb[j * 3] - cx, dy = xb[j * 3 + 1] - cy, dz = xb[j * 3 + 2] - cz;
        float d = __fadd_rn(__fadd_rn(__fmul_rn(dx, dx), __fmul_rn(dy, dy)), __fmul_rn(dz, dz));
        unsigned m = __ballot_sync(0xffffffffu, d < 0.09f);
        if (lane == 0) {
            while (m && cnt < NSAMP) { int t = __ffs(m) - 1; buf[cnt++] = c0 + t; m &= m - 1; }
        }
        cnt = __shfl_sync(0xffffffffu, cnt, 0);
        if (cnt >= NSAMP) break;
    }
    if (lane == 0) {
        const int f = (cnt > 0) ? buf[0] : (NPTS - 1);
        for (int s = cnt; s < NSAMP; s++) buf[s] = f;
        for (int s = 0; s < NSAMP; s++) g_idx[gw * NSAMP + s] = buf[s];
    }
    // tail: new_xyz + inds into output (g_newxyz/g_inds final after pre_kernel)
    const int gt = blockIdx.x * blockDim.x + threadIdx.x;
    if (gt < 24576) out[OFF_NEWXYZ + gt] = g_newxyz[gt];
    else if (gt < 32768) out[OFF_INDS + gt - 24576] = (float)g_inds[gt - 24576];
}

// ---------------- mma MLP: layer-0 A from gmem, layers 1-2 A in smem ----------
__global__ __launch_bounds__(128, 4) void mlp_kernel(
    const float* __restrict__ xyz, const float* __restrict__ feats,
    const float* __restrict__ b0, const float* __restrict__ gg0, const float* __restrict__ be0,
    const float* __restrict__ b1, const float* __restrict__ gg1, const float* __restrict__ be1,
    const float* __restrict__ b2, const float* __restrict__ gg2, const float* __restrict__ be2) {
    extern __shared__ __align__(16) char dsm[];
    __nv_bfloat16* Ah = (__nv_bfloat16*)dsm;            // 64 x LDB
    __nv_bfloat16* Al = Ah + 64 * LDB;
    __shared__ int   s_j[64];
    __shared__ float s_gx[64][3];

    const int tid = threadIdx.x, w = tid >> 5, lane = tid & 31;
    const int p = blockIdx.x * 4 + w;
    const int b = p >> 8;
    const int g = lane >> 2, t = lane & 3;

    // gather indices + gxyz (lanes 0-15 own rows)
    if (lane < 16) {
        const int row = w * 16 + lane;
        const int j = g_idx[p * NSAMP + lane];
        s_j[row] = j;
        const float* np = g_newxyz + p * 3;
        const float* xp = xyz + ((size_t)b * NPTS + j) * 3;
        #pragma unroll
        for (int c = 0; c < 3; c++)
            s_gx[row][c] = __fdiv_rn(xp[c] - np[c], 0.3f);
    }
    __syncwarp();

    float acc[16][4];
    #pragma unroll
    for (int j = 0; j < 16; j++)
        acc[j][0] = acc[j][1] = acc[j][2] = acc[j][3] = 0.f;

    // ---- layer 0: A fragments straight from gmem (17 chunks) ----
    {
        const float* fb = feats + (size_t)b * NPTS * NCH;
        const float* rowA = fb + (size_t)s_j[w * 16 + g] * NCH;
        const float* rowB = fb + (size_t)s_j[w * 16 + g + 8] * NCH;
        const uint2* Wh = (const uint2*)g_W0p[0];
        const uint2* Wl = (const uint2*)g_W0p[1];
        for (int c = 0; c < 17; c++) {
            uint32_t ah[4], al[4];
            if (c < 16) {
                const float2 a0 = __ldg((const float2*)(rowA + c * 16 + 2 * t));
                const float2 a1 = __ldg((const float2*)(rowB + c * 16 + 2 * t));
                const float2 a2 = __ldg((const float2*)(rowA + c * 16 + 8 + 2 * t));
                const float2 a3 = __ldg((const float2*)(rowB + c * 16 + 8 + 2 * t));
                ah[0] = pack_bf2(a0.x, a0.y); al[0] = pack_lo2(a0.x, a0.y);
                ah[1] = pack_bf2(a1.x, a1.y); al[1] = pack_lo2(a1.x, a1.y);
                ah[2] = pack_bf2(a2.x, a2.y); al[2] = pack_lo2(a2.x, a2.y);
                ah[3] = pack_bf2(a3.x, a3.y); al[3] = pack_lo2(a3.x, a3.y);
            } else {
                // cols 256-271: 256,257,258 = gxyz, rest 0
                const float* gA = s_gx[w * 16 + g];
                const float* gB = s_gx[w * 16 + g + 8];
                const float v0A = (t == 0) ? gA[0] : (t == 1) ? gA[2] : 0.f;
                const float v1A = (t == 0) ? gA[1] : 0.f;
                const float v0B = (t == 0) ? gB[0] : (t == 1) ? gB[2] : 0.f;
                const float v1B = (t == 0) ? gB[1] : 0.f;
                ah[0] = pack_bf2(v0A, v1A); al[0] = pack_lo2(v0A, v1A);
                ah[1] = pack_bf2(v0B, v1B); al[1] = pack_lo2(v0B, v1B);
                ah[2] = 0; al[2] = 0;
                ah[3] = 0; al[3] = 0;
            }
            chunk_mma<16>(acc, ah, al, Wh, Wl, c, lane);
        }
    }
    epi_generic<false>(acc, Ah, Al, b0, gg0, be0, w, lane);

    const uint32_t aOff = ((w * 16 + (lane & 15)) * LDB + (lane >> 4) * 8) * 2;
    const uint32_t aH = smem_u32(Ah) + aOff;
    const uint32_t aL = smem_u32(Al) + aOff;

    run_layer_sm<16>(acc, aH, aL, (const uint2*)g_W1p[0], (const uint2*)g_W1p[1], 8, lane);
    epi_generic<false>(acc, Ah, Al, b1, gg1, be1, w, lane);
    run_layer_sm<16>(acc, aH, aL, (const uint2*)g_W2p[0], (const uint2*)g_W2p[1], 8, lane);

    // maxpool epilogue
    {
        #pragma unroll
        for (int j = 0; j < 16; j++) {
            const int n0 = j * 8 + t * 2, n1 = n0 + 1;
            const float g0 = __ldg(gg2 + n0), g1 = __ldg(gg2 + n1);
            const float c0 = __ldg(b2 + n0), c1 = __ldg(b2 + n1);
            const float e0 = __ldg(be2 + n0), e1 = __ldg(be2 + n1);
            float m0 = fmaxf(fmaxf(g0 * (acc[j][0] + c0) + e0, 0.f),
                             fmaxf(g0 * (acc[j][2] + c0) + e0, 0.f));
            float m1 = fmaxf(fmaxf(g1 * (acc[j][1] + c1) + e1, 0.f),
                             fmaxf(g1 * (acc[j][3] + c1) + e1, 0.f));
            #pragma unroll
            for (int o = 4; o <= 16; o <<= 1) {
                m0 = fmaxf(m0, __shfl_xor_sync(0xffffffffu, m0, o));
                m1 = fmaxf(m1, __shfl_xor_sync(0xffffffffu, m1, o));
            }
            if (lane < 4)
                *(float2*)(g_feat + ((size_t)p << 7) + n0) = make_float2(m0, m1);
        }
    }
}

// ---------------- mma head (verified R6) ----------------
__device__ __forceinline__ void scatter_out(float* __restrict__ out, int gp, int n,
                                            float v, const float* __restrict__ msz) {
    if (n >= OUTCH) return;
    if (n < 3) {
        out[OFF_CENTER + gp * 3 + n] = g_newxyz[gp * 3 + n] + v;
        return;
    }
    const int jr = n - 3;
    if (jr < 2)       out[OFF_OBJ + gp * 2 + jr] = v;
    else if (jr < 14) out[OFF_HS + gp * 12 + (jr - 2)] = v;
    else if (jr < 32) out[OFF_SS + gp * 18 + (jr - 14)] = v;
    else if (jr < 44) {
        const int h = jr - 32;
        out[OFF_HRN + gp * 12 + h] = v;
        out[OFF_HR + gp * 12 + h] = v * 0.26179938779916667f;
    } else if (jr < 98) {
        const int t = jr - 44;
        out[OFF_SRN + gp * 54 + t] = v;
        out[OFF_SR + gp * 54 + t] = v * __ldg(msz + t);
    } else out[OFF_SEM + gp * 18 + (jr - 98)] = v;
}

__global__ __launch_bounds__(128, 3) void head_kernel(
    const float* __restrict__ b1, const float* __restrict__ gg1, const float* __restrict__ be1,
    const float* __restrict__ b2, const float* __restrict__ gg2, const float* __restrict__ be2,
    const float* __restrict__ b3, const float* __restrict__ msz, float* __restrict__ out) {
    extern __shared__ __align__(16) char dsm[];
    __nv_bfloat16* Ah = (__nv_bfloat16*)dsm;        // 64 x LDB
    __nv_bfloat16* Al = Ah + 64 * LDB;

    const int tid = threadIdx.x, w = tid >> 5, lane = tid & 31;
    const int gp0 = blockIdx.x * 64;

    #pragma unroll 1
    for (int r = 0; r < 16; r++) {
        const int row = w * 16 + r;
        const float4 f = ((const float4*)(g_feat + ((size_t)(gp0 + row) << 7)))[lane];
        uint2 H, L;
        H.x = pack_bf2(f.x, f.y); H.y = pack_bf2(f.z, f.w);
        L.x = pack_lo2(f.x, f.y); L.y = pack_lo2(f.z, f.w);
        *(uint2*)(Ah + row * LDB + lane * 4) = H;
        *(uint2*)(Al + row * LDB + lane * 4) = L;
    }
    __syncwarp();

    float acc[16][4];
    #pragma unroll
    for (int j = 0; j < 16; j++)
        acc[j][0] = acc[j][1] = acc[j][2] = acc[j][3] = 0.f;

    const uint32_t aOff = ((w * 16 + (lane & 15)) * LDB + (lane >> 4) * 8) * 2;
    const uint32_t aH = smem_u32(Ah) + aOff;
    const uint32_t aL = smem_u32(Al) + aOff;

    run_layer_sm<16>(acc, aH, aL, (const uint2*)g_H1p[0], (const uint2*)g_H1p[1], 8, lane);
    epi_generic<true>(acc, Ah, Al, b1, gg1, be1, w, lane);
    run_layer_sm<16>(acc, aH, aL, (const uint2*)g_H2p[0], (const uint2*)g_H2p[1], 8, lane);
    epi_generic<true>(acc, Ah, Al, b2, gg2, be2, w, lane);
    {
        // layer 3: NJ=15
        float acc3[15][4];
        #pragma unroll
        for (int j = 0; j < 15; j++)
            acc3[j][0] = acc3[j][1] = acc3[j][2] = acc3[j][3] = 0.f;
        run_layer_sm<15>(acc3, aH, aL, (const uint2*)g_H3p[0], (const uint2*)g_H3p[1], 8, lane);
        const int g = lane >> 2, t = lane & 3;
        const int gpA = gp0 + w * 16 + g, gpB = gpA + 8;
        #pragma unroll
        for (int j = 0; j < 15; j++) {
            const int n0 = j * 8 + t * 2, n1 = n0 + 1;
            const float bb0 = (n0 < OUTCH) ? __ldg(b3 + n0) : 0.f;
            const float bb1 = (n1 < OUTCH) ? __ldg(b3 + n1) : 0.f;
            scatter_out(out, gpA, n0, acc3[j][0] + bb0, msz);
            scatter_out(out, gpA, n1, acc3[j][1] + bb1, msz);
            scatter_out(out, gpB, n0, acc3[j][2] + bb0, msz);
            scatter_out(out, gpB, n1, acc3[j][3] + bb1, msz);
        }
    }
}

extern "C" void kernel_launch(void* const* d_in, const int* in_sizes, int n_in,
                              void* d_out, int out_size) {
    const float* xyz   = (const float*)d_in[0];
    const float* feats = (const float*)d_in[1];
    const float* msz   = (const float*)d_in[2];
    const float* w_m0  = (const float*)d_in[3];
    const float* b_m0  = (const float*)d_in[4];
    const float* g_m0  = (const float*)d_in[5];
    const float* be_m0 = (const float*)d_in[6];
    const float* w_m1  = (const float*)d_in[7];
    const float* b_m1  = (const float*)d_in[8];
    const float* g_m1  = (const float*)d_in[9];
    const float* be_m1 = (const float*)d_in[10];
    const float* w_m2  = (const float*)d_in[11];
    const float* b_m2  = (const float*)d_in[12];
    const float* g_m2  = (const float*)d_in[13];
    const float* be_m2 = (const float*)d_in[14];
    const float* w1    = (const float*)d_in[15];
    const float* b1    = (const float*)d_in[16];
    const float* g1    = (const float*)d_in[17];
    const float* be1   = (const float*)d_in[18];
    const float* w2    = (const float*)d_in[19];
    const float* b2    = (const float*)d_in[20];
    const float* g2    = (const float*)d_in[21];
    const float* be2   = (const float*)d_in[22];
    const float* w3    = (const float*)d_in[23];
    const float* b3    = (const float*)d_in[24];
    float* out = (float*)d_out;

    cudaFuncSetAttribute(mlp_kernel, cudaFuncAttributeMaxDynamicSharedMemorySize, MLP_SMEM);
    cudaFuncSetAttribute(head_kernel, cudaFuncAttributeMaxDynamicSharedMemorySize, HEAD_SMEM);

    pre_kernel<<<288, 256>>>(xyz, w_m0, w_m1, w_m2, w1, w2, w3);
    ball_kernel<<<(NBATCH * NPROP * 32) / 256, 256>>>(xyz, out);
    mlp_kernel<<<NBATCH * NPROP / 4, 128, MLP_SMEM>>>(
        xyz, feats, b_m0, g_m0, be_m0, b_m1, g_m1, be_m1, b_m2, g_m2, be_m2);
    head_kernel<<<(NBATCH * NPROP) / 64, 128, HEAD_SMEM>>>(
        b1, g1, be1, b2, g2, be2, b3, msz, out);
}